// round 15
// baseline (speedup 1.0000x reference)
#include <cuda_runtime.h>
#include <math.h>
#include <stdint.h>

#define Nn   1024
#define Dd   256
#define Hh   8
#define DKk  32
#define FFf  1024
#define Rr   37
#define Ll   8
#define EPSf 1e-6f
#define SCALEf 0.17677669529663687f  /* 1/sqrt(32) */

// ---------------- scratch (device globals: no allocation allowed) ----------------
__device__ float g_X [Nn*Dd];
__device__ float g_Q [Nn*Dd];
__device__ float g_K [Nn*Dd];
__device__ float g_V [Nn*Dd];
__device__ float g_O [Nn*Dd];
__device__ float g_FF[Nn*FFf];
__device__ unsigned char g_rel8[Nn*Nn];
// tf32-pre-rounded weights
__device__ float g_Wq[Ll*Dd*Dd];
__device__ float g_Wk[Ll*Dd*Dd];
__device__ float g_Wv[Ll*Dd*Dd];
__device__ float g_Wo[Ll*Dd*Dd];
__device__ float g_W1[Ll*Dd*FFf];
__device__ float g_W2[Ll*FFf*Dd];

// ---------------- tf32 helpers -----------------------------------------------------
__device__ __forceinline__ uint32_t f2tf(float f) {
    uint32_t u; asm("cvt.rna.tf32.f32 %0, %1;" : "=r"(u) : "f"(f)); return u;
}
__device__ __forceinline__ float tfr(float f) { return __uint_as_float(f2tf(f)); }
__device__ __forceinline__ void mma_tf32(float* d, const uint32_t* a, const uint32_t* b) {
    asm volatile("mma.sync.aligned.m16n8k8.row.col.f32.tf32.tf32.f32 "
        "{%0,%1,%2,%3}, {%4,%5,%6,%7}, {%8,%9}, {%0,%1,%2,%3};\n"
        : "+f"(d[0]), "+f"(d[1]), "+f"(d[2]), "+f"(d[3])
        : "r"(a[0]), "r"(a[1]), "r"(a[2]), "r"(a[3]), "r"(b[0]), "r"(b[1]));
}

// ---------------- one-time prep (single kernel: rel->u8 + weight rounding) ----------
#define SZ_D (Ll*Dd*Dd/4)
#define SZ_F (Ll*Dd*FFf/4)
#define SZ_R (Nn*Nn/4)
__global__ void prep_kernel(const int* __restrict__ rel, unsigned char* __restrict__ r8,
                            const float* __restrict__ Wq, const float* __restrict__ Wk,
                            const float* __restrict__ Wv, const float* __restrict__ Wo,
                            const float* __restrict__ W1, const float* __restrict__ W2,
                            float* __restrict__ oq, float* __restrict__ ok,
                            float* __restrict__ ov, float* __restrict__ oo,
                            float* __restrict__ o1, float* __restrict__ o2) {
    const int total = 4*SZ_D + 2*SZ_F + SZ_R;
    for (int i = blockIdx.x*256 + threadIdx.x; i < total; i += gridDim.x*256) {
        int j = i;
        if (j < SZ_R) {   // 4 rel ints -> 4 bytes
            int4 v = ((const int4*)rel)[j];
            uchar4 o; o.x=(unsigned char)v.x; o.y=(unsigned char)v.y;
            o.z=(unsigned char)v.z; o.w=(unsigned char)v.w;
            ((uchar4*)r8)[j] = o;
            continue;
        }
        j -= SZ_R;
        const float4* s; float4* d;
        if      (j < SZ_D)            { s = (const float4*)Wq; d = (float4*)oq; }
        else if ((j -= SZ_D) < SZ_D)  { s = (const float4*)Wk; d = (float4*)ok; }
        else if ((j -= SZ_D) < SZ_D)  { s = (const float4*)Wv; d = (float4*)ov; }
        else if ((j -= SZ_D) < SZ_D)  { s = (const float4*)Wo; d = (float4*)oo; }
        else if ((j -= SZ_D) < SZ_F)  { s = (const float4*)W1; d = (float4*)o1; }
        else    { j -= SZ_F;            s = (const float4*)W2; d = (float4*)o2; }
        float4 v = s[j];
        d[j] = make_float4(tfr(v.x), tfr(v.y), tfr(v.z), tfr(v.w));
    }
}

// ---------------- final LayerNorm ---------------------------------------------------
__global__ void ln_kernel(const float* __restrict__ in, float* __restrict__ out,
                          const float* __restrict__ g, const float* __restrict__ b) {
    const int wid = threadIdx.x >> 5, lane = threadIdx.x & 31;
    const int row = blockIdx.x * 8 + wid;
    const float* p = in + (size_t)row * Dd + lane * 8;
    float4 v1 = *(const float4*)p, v2 = *(const float4*)(p + 4);
    float s = v1.x+v1.y+v1.z+v1.w + v2.x+v2.y+v2.z+v2.w;
    #pragma unroll
    for (int o = 16; o > 0; o >>= 1) s += __shfl_xor_sync(0xffffffffu, s, o);
    const float mu = s * (1.f/Dd);
    float d0=v1.x-mu,d1=v1.y-mu,d2=v1.z-mu,d3=v1.w-mu;
    float d4=v2.x-mu,d5=v2.y-mu,d6=v2.z-mu,d7=v2.w-mu;
    float q = d0*d0+d1*d1+d2*d2+d3*d3+d4*d4+d5*d5+d6*d6+d7*d7;
    #pragma unroll
    for (int o = 16; o > 0; o >>= 1) q += __shfl_xor_sync(0xffffffffu, q, o);
    const float inv = 1.f / (sqrtf(q * (1.f/(Dd-1))) + EPSf);
    const int c = lane * 8;
    float* op = out + (size_t)row * Dd + c;
    *(float4*)op = make_float4(g[c+0]*d0*inv+b[c+0], g[c+1]*d1*inv+b[c+1],
                               g[c+2]*d2*inv+b[c+2], g[c+3]*d3*inv+b[c+3]);
    *(float4*)(op+4) = make_float4(g[c+4]*d4*inv+b[c+4], g[c+5]*d5*inv+b[c+5],
                                   g[c+6]*d6*inv+b[c+6], g[c+7]*d7*inv+b[c+7]);
}

// ---------------- tf32 MMA GEMM: 32xBN tile, BK=32, 256 threads (8 warps 2x4) -------
// AREG (with LNA) keeps A in registers; non-AREG path uses LDG prefetch and DUAL
// accumulator banks (kk parity) to halve the mma dependency chain.
template<bool RELU, bool RES, bool ROUND, bool LNA, bool AREG, int BN>
__device__ __forceinline__ void gemm_body(
    const float* __restrict__ A, int lda, const float* __restrict__ B, int ldb,
    const float* __restrict__ bias, const float* __restrict__ res,
    float* __restrict__ C, int ldc, int K, int m0, int n0,
    const float* __restrict__ lg, const float* __restrict__ lb)
{
    constexpr int SB = BN + 8;
    constexpr int NS = BN / 32;
    constexpr int BV = BN / 8;
    __shared__ float As[2][32*36];
    __shared__ float Bs[2][32*SB];
    const int tid = threadIdx.x, lane = tid & 31, wid = tid >> 5;
    const int g = lane >> 2, tt = lane & 3;
    const int wm = wid >> 2, wn = wid & 3;
    const int ar = tid >> 3, acol = (tid & 7) * 4;
    const int bkr = tid >> 3;
    const int bnc = (tid & 7) * BV;

    // AREG path: single accumulator bank (register pressure). non-AREG: dual banks.
    float acc[AREG ? 1 : 2][NS][4];
    #pragma unroll
    for (int p = 0; p < (AREG ? 1 : 2); p++)
        #pragma unroll
        for (int j = 0; j < NS; j++)
            #pragma unroll
            for (int q = 0; q < 4; q++) acc[p][j][q] = 0.f;

    const float* Aptr = A + (size_t)(m0 + ar)*lda + acol;
    const float* Bptr = B + (size_t)bkr*ldb + n0 + bnc;

    float areg[AREG ? 32 : 4];
    if (AREG) {
        #pragma unroll
        for (int c = 0; c < 8; c++)
            *(float4*)&areg[c*4] = *(const float4*)(Aptr + c*32);
        if (LNA) {
            float s = 0.f;
            #pragma unroll
            for (int i = 0; i < 32; i++) s += areg[i];
            #pragma unroll
            for (int o = 1; o < 8; o <<= 1) s += __shfl_xor_sync(0xffffffffu, s, o);
            const float mu = s * (1.f/Dd);
            float q = 0.f;
            #pragma unroll
            for (int i = 0; i < 32; i++) { float d = areg[i]-mu; q += d*d; }
            #pragma unroll
            for (int o = 1; o < 8; o <<= 1) q += __shfl_xor_sync(0xffffffffu, q, o);
            const float inv = 1.f / (sqrtf(q * (1.f/(Dd-1))) + EPSf);
            #pragma unroll
            for (int c = 0; c < 8; c++) {
                float4 g4 = *(const float4*)(lg + c*32 + acol);
                float4 b4 = *(const float4*)(lb + c*32 + acol);
                areg[c*4+0] = tfr(g4.x*(areg[c*4+0]-mu)*inv + b4.x);
                areg[c*4+1] = tfr(g4.y*(areg[c*4+1]-mu)*inv + b4.y);
                areg[c*4+2] = tfr(g4.z*(areg[c*4+2]-mu)*inv + b4.z);
                areg[c*4+3] = tfr(g4.w*(areg[c*4+3]-mu)*inv + b4.w);
            }
        }
    }

    {
        if (AREG) {
            *(float4*)&As[0][ar*36 + acol] = *(float4*)&areg[0];
        } else {
            *(float4*)&As[0][ar*36 + acol] = *(const float4*)Aptr;
        }
        *(float4*)&Bs[0][bkr*SB + bnc] = *(const float4*)Bptr;
        if (BV == 8) *(float4*)&Bs[0][bkr*SB + bnc + 4] = *(const float4*)(Bptr + 4);
    }
    __syncthreads();

    if (AREG) {
        #pragma unroll
        for (int kt = 0; kt < 8; kt++) {
            const int cur = kt & 1;
            const bool nx = kt < 7;
            float4 pb0, pb1;
            if (nx) {
                const float* bp = Bptr + (size_t)(kt+1)*32*ldb;
                pb0 = *(const float4*)bp;
                if (BV == 8) pb1 = *(const float4*)(bp + 4);
            }
            #pragma unroll
            for (int kk = 0; kk < 4; kk++) {
                const int k = kk*8, mb = wm*16;
                uint32_t af[4];
                af[0] = __float_as_uint(As[cur][(mb+g)*36   + k+tt]);
                af[1] = __float_as_uint(As[cur][(mb+g+8)*36 + k+tt]);
                af[2] = __float_as_uint(As[cur][(mb+g)*36   + k+tt+4]);
                af[3] = __float_as_uint(As[cur][(mb+g+8)*36 + k+tt+4]);
                #pragma unroll
                for (int sn = 0; sn < NS; sn++) {
                    const int nb = wn*(BN/4) + sn*8;
                    uint32_t bf[2];
                    bf[0] = __float_as_uint(Bs[cur][(k+tt)*SB + nb+g]);
                    bf[1] = __float_as_uint(Bs[cur][(k+tt+4)*SB + nb+g]);
                    mma_tf32(acc[0][sn], af, bf);
                }
            }
            if (nx) {
                const int nxt = cur ^ 1;
                *(float4*)&As[nxt][ar*36 + acol] = *(float4*)&areg[(kt+1)*4];
                *(float4*)&Bs[nxt][bkr*SB + bnc] = pb0;
                if (BV == 8) *(float4*)&Bs[nxt][bkr*SB + bnc + 4] = pb1;
            }
            __syncthreads();
        }
    } else {
        const int nkt = K / 32;
        for (int kt = 0; kt < nkt; kt++) {
            const int cur = kt & 1;
            const bool nx = (kt + 1) < nkt;
            float4 pa, pb0, pb1;
            if (nx) {
                pa = *(const float4*)(Aptr + (kt+1)*32);
                const float* bp = Bptr + (size_t)(kt+1)*32*ldb;
                pb0 = *(const float4*)bp;
                if (BV == 8) pb1 = *(const float4*)(bp + 4);
            }
            #pragma unroll
            for (int kk = 0; kk < 4; kk++) {
                const int k = kk*8, mb = wm*16;
                uint32_t af[4];
                af[0] = __float_as_uint(As[cur][(mb+g)*36   + k+tt]);
                af[1] = __float_as_uint(As[cur][(mb+g+8)*36 + k+tt]);
                af[2] = __float_as_uint(As[cur][(mb+g)*36   + k+tt+4]);
                af[3] = __float_as_uint(As[cur][(mb+g+8)*36 + k+tt+4]);
                #pragma unroll
                for (int sn = 0; sn < NS; sn++) {
                    const int nb = wn*(BN/4) + sn*8;
                    uint32_t bf[2];
                    bf[0] = __float_as_uint(Bs[cur][(k+tt)*SB + nb+g]);
                    bf[1] = __float_as_uint(Bs[cur][(k+tt+4)*SB + nb+g]);
                    mma_tf32(acc[kk & 1][sn], af, bf);
                }
            }
            if (nx) {
                const int nxt = cur ^ 1;
                *(float4*)&As[nxt][ar*36 + acol] = pa;
                *(float4*)&Bs[nxt][bkr*SB + bnc] = pb0;
                if (BV == 8) *(float4*)&Bs[nxt][bkr*SB + bnc + 4] = pb1;
            }
            __syncthreads();
        }
    }

    const int r0 = m0 + wm*16 + g;
    #pragma unroll
    for (int sn = 0; sn < NS; sn++) {
        const int cg = n0 + wn*(BN/4) + sn*8 + tt*2;
        float v0, v1, v2, v3;
        if (AREG) {
            v0 = acc[0][sn][0]; v1 = acc[0][sn][1];
            v2 = acc[0][sn][2]; v3 = acc[0][sn][3];
        } else {
            v0 = acc[0][sn][0] + acc[1][sn][0];
            v1 = acc[0][sn][1] + acc[1][sn][1];
            v2 = acc[0][sn][2] + acc[1][sn][2];
            v3 = acc[0][sn][3] + acc[1][sn][3];
        }
        v0 += bias[cg]; v1 += bias[cg+1]; v2 += bias[cg]; v3 += bias[cg+1];
        if (RELU) { v0 = fmaxf(v0,0.f); v1 = fmaxf(v1,0.f); v2 = fmaxf(v2,0.f); v3 = fmaxf(v3,0.f); }
        if (ROUND) { v0 = tfr(v0); v1 = tfr(v1); v2 = tfr(v2); v3 = tfr(v3); }
        if (RES) {
            v0 += res[(size_t)r0*ldc + cg];     v1 += res[(size_t)r0*ldc + cg+1];
            v2 += res[(size_t)(r0+8)*ldc + cg]; v3 += res[(size_t)(r0+8)*ldc + cg+1];
        }
        *(float2*)&C[(size_t)r0*ldc + cg]     = make_float2(v0, v1);
        *(float2*)&C[(size_t)(r0+8)*ldc + cg] = make_float2(v2, v3);
    }
}

template<bool RELU, bool RES, bool ROUND, bool LNA, bool AREG, int BN>
__global__ void __launch_bounds__(256)
gemm_kernel(const float* __restrict__ A, int lda,
            const float* __restrict__ B, int ldb,
            const float* __restrict__ bias,
            const float* __restrict__ res,
            float* __restrict__ C, int ldc, int K,
            const float* __restrict__ lg,
            const float* __restrict__ lb) {
    gemm_body<RELU, RES, ROUND, LNA, AREG, BN>(A, lda, B, ldb, bias, res, C, ldc, K,
                                               blockIdx.y*32, blockIdx.x*BN, lg, lb);
}

__global__ void __launch_bounds__(256)
qkv_kernel(const float* __restrict__ A,
           const float* __restrict__ Wq, const float* __restrict__ Wk,
           const float* __restrict__ Wv,
           const float* __restrict__ bq, const float* __restrict__ bk,
           const float* __restrict__ bv,
           float* __restrict__ Q, float* __restrict__ Km,
           float* __restrict__ V,
           const float* __restrict__ lg,
           const float* __restrict__ lb) {
    const float* B; const float* bias; float* C;
    if (blockIdx.z == 0)      { B = Wq; bias = bq; C = Q;  }
    else if (blockIdx.z == 1) { B = Wk; bias = bk; C = Km; }
    else                      { B = Wv; bias = bv; C = V;  }
    gemm_body<false, false, true, true, true, 64>(A, Dd, B, Dd, bias, nullptr, C, Dd, Dd,
                                                  blockIdx.y*32, blockIdx.x*64, lg, lb);
}

// ---------------- fused relational flash attention: register-P PV (R11 winner) ------
#define BINSTRIDE 1188
__global__ void __launch_bounds__(256, 3)
flash_kernel(const float* __restrict__ Q, const float* __restrict__ Kg,
             const float* __restrict__ Vg,
             const unsigned char* __restrict__ rel8,
             const float* __restrict__ rke, const float* __restrict__ rve,
             float* __restrict__ O)
{
    extern __shared__ float smf[];
    float* Qs    = smf;                 // 32*36
    float* Ks    = Qs    + 32*36;       // 64*36
    float* Vs    = Ks    + 64*36;       // 64*40 (row-permuted)
    float* Ps    = Vs    + 64*40;       // 32*68
    float* qrs   = Ps    + 32*68;       // 32*37 (reused as merged bins)
    float* bins  = qrs   + 32*Rr;       // 4*BINSTRIDE
    float* rks   = bins  + 4*BINSTRIDE; // 37*32
    float* rvs   = rks   + Rr*DKk;      // 37*32
    float* lredS = rvs   + Rr*DKk;      // 128
    float* lrow  = lredS + 128;         // 32
    float* osA   = lrow  + 32;          // 1024
    float* osB   = osA   + 1024;        // 1024

    const int tid  = threadIdx.x;
    const int lane = tid & 31, wid = tid >> 5;
    const int g = lane >> 2, tt = lane & 3;
    const int i0 = blockIdx.x * 32, h = blockIdx.y;
    const int s_wm = wid >> 2, s_wn = wid & 3;

    const int kvr = tid >> 2, kvd = (tid & 3) * 8;
    const int vpr = (kvr & ~7) | ((kvr & 7) >> 1) | ((kvr & 1) << 2);
    const uint32_t ks_a0 = (uint32_t)__cvta_generic_to_shared(&Ks[kvr*36 + kvd]);
    const uint32_t ks_a1 = ks_a0 + 16;
    const uint32_t vs_a0 = (uint32_t)__cvta_generic_to_shared(&Vs[vpr*40 + kvd]);
    const uint32_t vs_a1 = vs_a0 + 16;

    // ---- init ----
    {
        const int r = tid >> 3, dc = (tid & 7) * 4;
        *(float4*)&Qs[r*36 + dc] = *(const float4*)(Q + (size_t)(i0+r)*Dd + h*DKk + dc);
    }
    for (int idx = tid; idx < Rr*DKk; idx += 256) { rks[idx] = rke[idx]; rvs[idx] = rve[idx]; }
    for (int idx = tid; idx < 4*BINSTRIDE; idx += 256) bins[idx] = 0.f;
    __syncthreads();

    for (int p = tid; p < 32*Rr; p += 256) {
        const int row = p / Rr, r = p - row*Rr;
        const float* qrow = Qs + row*36;
        const float* kr   = rks + r*DKk;
        float s = 0.f;
        #pragma unroll
        for (int d = 0; d < DKk; d++) s += qrow[d]*kr[d];
        qrs[row*Rr + r] = s;
    }

    uint32_t af[4][4];
    {
        const int mb = s_wm*16;
        #pragma unroll
        for (int ks = 0; ks < 4; ks++) {
            af[ks][0] = __float_as_uint(Qs[(mb+g)*36   + ks*8+tt]);
            af[ks][1] = __float_as_uint(Qs[(mb+g+8)*36 + ks*8+tt]);
            af[ks][2] = __float_as_uint(Qs[(mb+g)*36   + ks*8+tt+4]);
            af[ks][3] = __float_as_uint(Qs[(mb+g+8)*36 + ks*8+tt+4]);
        }
    }
    float oacc[4][4];
    #pragma unroll
    for (int i = 0; i < 4; i++)
        #pragma unroll
        for (int j = 0; j < 4; j++) oacc[i][j] = 0.f;
    float lp0 = 0.f, lp1 = 0.f;
    const int r0f = s_wm*16 + g, r1f = r0f + 8;

    // prologue: stage K/V tile 0 (V permuted)
    {
        const float* kp = Kg + (size_t)kvr*Dd + h*DKk + kvd;
        const float* vp = Vg + (size_t)kvr*Dd + h*DKk + kvd;
        *(float4*)&Ks[kvr*36 + kvd]     = *(const float4*)kp;
        *(float4*)&Ks[kvr*36 + kvd + 4] = *(const float4*)(kp + 4);
        *(float4*)&Vs[vpr*40 + kvd]     = *(const float4*)vp;
        *(float4*)&Vs[vpr*40 + kvd + 4] = *(const float4*)(vp + 4);
    }
    __syncthreads();

    for (int jt = 0; jt < 16; jt++) {
        const int j0 = jt * 64;

        // S = Q @ K^T  (warp: 16 rows x 16 cols = its k-slice)
        float c[2][4];
        #pragma unroll
        for (int i = 0; i < 2; i++)
            #pragma unroll
            for (int j = 0; j < 4; j++) c[i][j] = 0.f;
        #pragma unroll
        for (int ks = 0; ks < 4; ks++) {
            #pragma unroll
            for (int sn = 0; sn < 2; sn++) {
                const int nb = s_wn*16 + sn*8;
                uint32_t bf[2];
                bf[0] = __float_as_uint(Ks[(nb+g)*36 + ks*8+tt]);
                bf[1] = __float_as_uint(Ks[(nb+g)*36 + ks*8+tt+4]);
                mma_tf32(c[sn], af[ks], bf);
            }
        }

        // exp in fragments; keep tf32 bits for PV A-frags; write Ps for bins pass
        uint32_t pb[2][4];
        {
            const unsigned char* rr0 = rel8 + (size_t)(i0+r0f)*Nn + j0;
            const unsigned char* rr1 = rel8 + (size_t)(i0+r1f)*Nn + j0;
            const float* q0 = qrs + r0f*Rr;
            const float* q1 = qrs + r1f*Rr;
            #pragma unroll
            for (int sn = 0; sn < 2; sn++) {
                const int col = s_wn*16 + sn*8 + tt*2;
                const unsigned int e0 = *(const unsigned short*)(rr0 + col);
                const unsigned int e1 = *(const unsigned short*)(rr1 + col);
                float p00 = __expf(fminf((c[sn][0] + q0[e0 & 0xff])*SCALEf, 80.f));
                float p01 = __expf(fminf((c[sn][1] + q0[e0 >> 8 ])*SCALEf, 80.f));
                float p10 = __expf(fminf((c[sn][2] + q1[e1 & 0xff])*SCALEf, 80.f));
                float p11 = __expf(fminf((c[sn][3] + q1[e1 >> 8 ])*SCALEf, 80.f));
                lp0 += p00 + p01; lp1 += p10 + p11;
                const uint32_t b00 = f2tf(p00), b01 = f2tf(p01);
                const uint32_t b10 = f2tf(p10), b11 = f2tf(p11);
                *(float2*)&Ps[r0f*68 + col] =
                    make_float2(__uint_as_float(b00), __uint_as_float(b01));
                *(float2*)&Ps[r1f*68 + col] =
                    make_float2(__uint_as_float(b10), __uint_as_float(b11));
                pb[sn][0] = b00; pb[sn][1] = b10; pb[sn][2] = b01; pb[sn][3] = b11;
            }
        }

        // O += P @ V' directly from registers: k-slice = own cols
        #pragma unroll
        for (int sn = 0; sn < 2; sn++) {
            const int k = s_wn*16 + sn*8;
            #pragma unroll
            for (int nb = 0; nb < 4; nb++) {
                uint32_t bf[2];
                bf[0] = __float_as_uint(Vs[(k+tt)*40 + nb*8+g]);
                bf[1] = __float_as_uint(Vs[(k+tt+4)*40 + nb*8+g]);
                mma_tf32(oacc[nb], pb[sn], bf);
            }
        }
        __syncthreads();   // sync1: Ps visible; Ks/Vs reads done

        // next K/V via cp.async — overlaps bins pass
        if (jt < 15) {
            const float* kp = Kg + (size_t)(j0+64+kvr)*Dd + h*DKk + kvd;
            const float* vp = Vg + (size_t)(j0+64+kvr)*Dd + h*DKk + kvd;
            asm volatile("cp.async.cg.shared.global [%0], [%1], 16;\n"
                         :: "r"(ks_a0), "l"(kp) : "memory");
            asm volatile("cp.async.cg.shared.global [%0], [%1], 16;\n"
                         :: "r"(ks_a1), "l"(kp + 4) : "memory");
            asm volatile("cp.async.cg.shared.global [%0], [%1], 16;\n"
                         :: "r"(vs_a0), "l"(vp) : "memory");
            asm volatile("cp.async.cg.shared.global [%0], [%1], 16;\n"
                         :: "r"(vs_a1), "l"(vp + 4) : "memory");
            asm volatile("cp.async.commit_group;\n" ::: "memory");
        }

        // bins: 128 threads, 4 replicas, exclusive (row, 16-col segment) — no atomics
        if (tid < 128) {
            const int rp_row = tid >> 2, rp_seg = tid & 3;
            const float* prow = Ps + rp_row*68 + rp_seg*16;
            float* bn = bins + rp_seg*BINSTRIDE + rp_row*Rr;
            uint4 rb = *(const uint4*)(rel8 + (size_t)(i0+rp_row)*Nn + j0 + rp_seg*16);
            const uint32_t rw[4] = {rb.x, rb.y, rb.z, rb.w};
            #pragma unroll
            for (int q4 = 0; q4 < 4; q4++) {
                float4 pv = *(const float4*)(prow + q4*4);
                const uint32_t r4 = rw[q4];
                bn[ r4      & 0xff] += pv.x;
                bn[(r4>> 8) & 0xff] += pv.y;
                bn[(r4>>16) & 0xff] += pv.z;
                bn[(r4>>24)       ] += pv.w;
            }
        }
        if (jt < 15) asm volatile("cp.async.wait_group 0;\n" ::: "memory");
        __syncthreads();   // sync2: bins done; staged K/V visible
    }

    // ---- reductions ----
    lp0 += __shfl_xor_sync(0xffffffffu, lp0, 1);
    lp0 += __shfl_xor_sync(0xffffffffu, lp0, 2);
    lp1 += __shfl_xor_sync(0xffffffffu, lp1, 1);
    lp1 += __shfl_xor_sync(0xffffffffu, lp1, 2);
    if ((lane & 3) == 0) { lredS[s_wn*32 + r0f] = lp0; lredS[s_wn*32 + r1f] = lp1; }
    if (s_wn == 1) {
        float* dst = osA + s_wm*512 + lane*16;
        #pragma unroll
        for (int nb = 0; nb < 4; nb++)
            #pragma unroll
            for (int q = 0; q < 4; q++) dst[nb*4+q] = oacc[nb][q];
    }
    __syncthreads();
    for (int idx = tid; idx < 32*Rr; idx += 256) {
        float s = 0.f;
        #pragma unroll
        for (int q = 0; q < 4; q++) s += bins[q*BINSTRIDE + idx];
        qrs[idx] = s;
    }
    if (tid < 32)
        lrow[tid] = lredS[tid] + lredS[32+tid] + lredS[64+tid] + lredS[96+tid];
    if (s_wn == 0) {
        const float* src = osA + s_wm*512 + lane*16;
        #pragma unroll
        for (int nb = 0; nb < 4; nb++)
            #pragma unroll
            for (int q = 0; q < 4; q++) oacc[nb][q] += src[nb*4+q];
    }
    if (s_wn == 2) {
        float* dst = osB + s_wm*512 + lane*16;
        #pragma unroll
        for (int nb = 0; nb < 4; nb++)
            #pragma unroll
            for (int q = 0; q < 4; q++) dst[nb*4+q] = oacc[nb][q];
    }
    __syncthreads();
    if (s_wn == 0) {
        const float* src = osB + s_wm*512 + lane*16;
        #pragma unroll
        for (int nb = 0; nb < 4; nb++)
            #pragma unroll
            for (int q = 0; q < 4; q++) oacc[nb][q] += src[nb*4+q];
    }
    if (s_wn == 3) {
        float* dst = osA + s_wm*512 + lane*16;
        #pragma unroll
        for (int nb = 0; nb < 4; nb++)
            #pragma unroll
            for (int q = 0; q < 4; q++) dst[nb*4+q] = oacc[nb][q];
    }
    __syncthreads();

    // ---- output: (P@V + bins@rv)/l, tf32-rounded (s_wn==0 warps) ----
    if (s_wn == 0) {
        const float* src = osA + s_wm*512 + lane*16;
        #pragma unroll
        for (int nb = 0; nb < 4; nb++)
            #pragma unroll
            for (int q = 0; q < 4; q++) oacc[nb][q] += src[nb*4+q];
        const float inv0 = 1.f / lrow[r0f];
        const float inv1 = 1.f / lrow[r1f];
        #pragma unroll
        for (int nb = 0; nb < 4; nb++) {
            const int col = nb*8 + tt*2;
            float s00 = 0.f, s01 = 0.f, s10 = 0.f, s11 = 0.f;
            #pragma unroll
            for (int r = 0; r < Rr; r++) {
                const float b0v = qrs[r0f*Rr+r], b1v = qrs[r1f*Rr+r];
                const float rv0 = rvs[r*DKk+col], rv1 = rvs[r*DKk+col+1];
                s00 += b0v*rv0; s01 += b0v*rv1; s10 += b1v*rv0; s11 += b1v*rv1;
            }
            *(float2*)&O[(size_t)(i0+r0f)*Dd + h*DKk + col] =
                make_float2(tfr((oacc[nb][0]+s00)*inv0), tfr((oacc[nb][1]+s01)*inv0));
            *(float2*)&O[(size_t)(i0+r1f)*Dd + h*DKk + col] =
                make_float2(tfr((oacc[nb][2]+s10)*inv1), tfr((oacc[nb][3]+s11)*inv1));
        }
    }
}

// ----------------------------------- host ------------------------------------------
#define FLASH_SMEM ((32*36 + 64*36 + 64*40 + 32*68 + 32*Rr + 4*BINSTRIDE \
                     + Rr*DKk + Rr*DKk + 128 + 32 + 2048) * 4)

extern "C" void kernel_launch(void* const* d_in, const int* in_sizes, int n_in,
                              void* d_out, int out_size) {
    const float* x    = (const float*)d_in[0];
    const int*   rel  = (const int*)  d_in[1];
    const float* Wq   = (const float*)d_in[2],  *bq = (const float*)d_in[3];
    const float* Wk   = (const float*)d_in[4],  *bk = (const float*)d_in[5];
    const float* Wv   = (const float*)d_in[6],  *bv = (const float*)d_in[7];
    const float* Wo   = (const float*)d_in[8],  *bo = (const float*)d_in[9];
    const float* rke  = (const float*)d_in[10], *rve = (const float*)d_in[11];
    const float* W1   = (const float*)d_in[12], *b1 = (const float*)d_in[13];
    const float* W2   = (const float*)d_in[14], *b2 = (const float*)d_in[15];
    const float* ln1g = (const float*)d_in[16], *ln1b = (const float*)d_in[17];
    const float* ln2g = (const float*)d_in[18], *ln2b = (const float*)d_in[19];
    const float* lnfg = (const float*)d_in[20], *lnfb = (const float*)d_in[21];

    float *X, *Q, *Kb, *V, *O, *FFb; unsigned char* R8;
    float *cWq, *cWk, *cWv, *cWo, *cW1, *cW2;
    cudaGetSymbolAddress((void**)&X,   g_X);
    cudaGetSymbolAddress((void**)&Q,   g_Q);
    cudaGetSymbolAddress((void**)&Kb,  g_K);
    cudaGetSymbolAddress((void**)&V,   g_V);
    cudaGetSymbolAddress((void**)&O,   g_O);
    cudaGetSymbolAddress((void**)&FFb, g_FF);
    cudaGetSymbolAddress((void**)&R8,  g_rel8);
    cudaGetSymbolAddress((void**)&cWq, g_Wq);
    cudaGetSymbolAddress((void**)&cWk, g_Wk);
    cudaGetSymbolAddress((void**)&cWv, g_Wv);
    cudaGetSymbolAddress((void**)&cWo, g_Wo);
    cudaGetSymbolAddress((void**)&cW1, g_W1);
    cudaGetSymbolAddress((void**)&cW2, g_W2);

    cudaFuncSetAttribute(flash_kernel, cudaFuncAttributeMaxDynamicSharedMemorySize, FLASH_SMEM);

    cudaMemcpyAsync(X, x, sizeof(float)*Nn*Dd, cudaMemcpyDeviceToDevice, 0);
    prep_kernel<<<2048, 256>>>(rel, R8, Wq, Wk, Wv, Wo, W1, W2,
                               cWq, cWk, cWv, cWo, cW1, cW2);

    for (int l = 0; l < Ll; l++) {
        qkv_kernel<<<dim3(Dd/64, Nn/32, 3), 256>>>(X,
            cWq + (size_t)l*Dd*Dd, cWk + (size_t)l*Dd*Dd, cWv + (size_t)l*Dd*Dd,
            bq + l*Dd, bk + l*Dd, bv + l*Dd, Q, Kb, V,
            ln1g + l*Dd, ln1b + l*Dd);
        flash_kernel<<<dim3(Nn/32, Hh), 256, FLASH_SMEM>>>(
            Q, Kb, V, R8, rke + (size_t)l*Rr*DKk, rve + (size_t)l*Rr*DKk, O);
        gemm_kernel<false, true, false, false, false, 32><<<dim3(Dd/32, Nn/32), 256>>>(
            O, Dd, cWo + (size_t)l*Dd*Dd, Dd, bo + l*Dd, X, X, Dd, Dd,
            nullptr, nullptr);
        gemm_kernel<true, false, true, true, true, 64><<<dim3(FFf/64, Nn/32), 256>>>(
            X, Dd, cW1 + (size_t)l*Dd*FFf, FFf, b1 + l*FFf, nullptr, FFb, FFf, Dd,
            ln2g + l*Dd, ln2b + l*Dd);
        gemm_kernel<false, true, false, false, false, 32><<<dim3(Dd/32, Nn/32), 256>>>(
            FFb, FFf, cW2 + (size_t)l*FFf*Dd, Dd, b2 + l*Dd, X, X, Dd, FFf,
            nullptr, nullptr);
    }
    ln_kernel<<<Nn/8, 256>>>(X, (float*)d_out, lnfg, lnfb);
}

// round 16
// speedup vs baseline: 1.0789x; 1.0789x over previous
#include <cuda_runtime.h>
#include <math.h>
#include <stdint.h>

#define Nn   1024
#define Dd   256
#define Hh   8
#define DKk  32
#define FFf  1024
#define Rr   37
#define Ll   8
#define EPSf 1e-6f
#define SCALEf 0.17677669529663687f  /* 1/sqrt(32) */

// ---------------- scratch (device globals: no allocation allowed) ----------------
__device__ float g_X [Nn*Dd];
__device__ float g_Q [Nn*Dd];
__device__ float g_K [Nn*Dd];
__device__ float g_V [Nn*Dd];
__device__ float g_O [Nn*Dd];
__device__ float g_FF[Nn*FFf];
__device__ unsigned char g_rel8[Nn*Nn];
// tf32-pre-rounded weights
__device__ float g_Wq[Ll*Dd*Dd];
__device__ float g_Wk[Ll*Dd*Dd];
__device__ float g_Wv[Ll*Dd*Dd];
__device__ float g_Wo[Ll*Dd*Dd];
__device__ float g_W1[Ll*Dd*FFf];
__device__ float g_W2[Ll*FFf*Dd];

// ---------------- tf32 helpers -----------------------------------------------------
__device__ __forceinline__ uint32_t f2tf(float f) {
    uint32_t u; asm("cvt.rna.tf32.f32 %0, %1;" : "=r"(u) : "f"(f)); return u;
}
__device__ __forceinline__ float tfr(float f) { return __uint_as_float(f2tf(f)); }
__device__ __forceinline__ void mma_tf32(float* d, const uint32_t* a, const uint32_t* b) {
    asm volatile("mma.sync.aligned.m16n8k8.row.col.f32.tf32.tf32.f32 "
        "{%0,%1,%2,%3}, {%4,%5,%6,%7}, {%8,%9}, {%0,%1,%2,%3};\n"
        : "+f"(d[0]), "+f"(d[1]), "+f"(d[2]), "+f"(d[3])
        : "r"(a[0]), "r"(a[1]), "r"(a[2]), "r"(a[3]), "r"(b[0]), "r"(b[1]));
}

// ---------------- one-time prep (single kernel: rel->u8 + weight rounding) ----------
#define SZ_D (Ll*Dd*Dd/4)
#define SZ_F (Ll*Dd*FFf/4)
#define SZ_R (Nn*Nn/4)
__global__ void prep_kernel(const int* __restrict__ rel, unsigned char* __restrict__ r8,
                            const float* __restrict__ Wq, const float* __restrict__ Wk,
                            const float* __restrict__ Wv, const float* __restrict__ Wo,
                            const float* __restrict__ W1, const float* __restrict__ W2,
                            float* __restrict__ oq, float* __restrict__ ok,
                            float* __restrict__ ov, float* __restrict__ oo,
                            float* __restrict__ o1, float* __restrict__ o2) {
    const int total = 4*SZ_D + 2*SZ_F + SZ_R;
    for (int i = blockIdx.x*256 + threadIdx.x; i < total; i += gridDim.x*256) {
        int j = i;
        if (j < SZ_R) {   // 4 rel ints -> 4 bytes
            int4 v = ((const int4*)rel)[j];
            uchar4 o; o.x=(unsigned char)v.x; o.y=(unsigned char)v.y;
            o.z=(unsigned char)v.z; o.w=(unsigned char)v.w;
            ((uchar4*)r8)[j] = o;
            continue;
        }
        j -= SZ_R;
        const float4* s; float4* d;
        if      (j < SZ_D)            { s = (const float4*)Wq; d = (float4*)oq; }
        else if ((j -= SZ_D) < SZ_D)  { s = (const float4*)Wk; d = (float4*)ok; }
        else if ((j -= SZ_D) < SZ_D)  { s = (const float4*)Wv; d = (float4*)ov; }
        else if ((j -= SZ_D) < SZ_D)  { s = (const float4*)Wo; d = (float4*)oo; }
        else if ((j -= SZ_D) < SZ_F)  { s = (const float4*)W1; d = (float4*)o1; }
        else    { j -= SZ_F;            s = (const float4*)W2; d = (float4*)o2; }
        float4 v = s[j];
        d[j] = make_float4(tfr(v.x), tfr(v.y), tfr(v.z), tfr(v.w));
    }
}

// ---------------- final LayerNorm ---------------------------------------------------
__global__ void ln_kernel(const float* __restrict__ in, float* __restrict__ out,
                          const float* __restrict__ g, const float* __restrict__ b) {
    const int wid = threadIdx.x >> 5, lane = threadIdx.x & 31;
    const int row = blockIdx.x * 8 + wid;
    const float* p = in + (size_t)row * Dd + lane * 8;
    float4 v1 = *(const float4*)p, v2 = *(const float4*)(p + 4);
    float s = v1.x+v1.y+v1.z+v1.w + v2.x+v2.y+v2.z+v2.w;
    #pragma unroll
    for (int o = 16; o > 0; o >>= 1) s += __shfl_xor_sync(0xffffffffu, s, o);
    const float mu = s * (1.f/Dd);
    float d0=v1.x-mu,d1=v1.y-mu,d2=v1.z-mu,d3=v1.w-mu;
    float d4=v2.x-mu,d5=v2.y-mu,d6=v2.z-mu,d7=v2.w-mu;
    float q = d0*d0+d1*d1+d2*d2+d3*d3+d4*d4+d5*d5+d6*d6+d7*d7;
    #pragma unroll
    for (int o = 16; o > 0; o >>= 1) q += __shfl_xor_sync(0xffffffffu, q, o);
    const float inv = 1.f / (sqrtf(q * (1.f/(Dd-1))) + EPSf);
    const int c = lane * 8;
    float* op = out + (size_t)row * Dd + c;
    *(float4*)op = make_float4(g[c+0]*d0*inv+b[c+0], g[c+1]*d1*inv+b[c+1],
                               g[c+2]*d2*inv+b[c+2], g[c+3]*d3*inv+b[c+3]);
    *(float4*)(op+4) = make_float4(g[c+4]*d4*inv+b[c+4], g[c+5]*d5*inv+b[c+5],
                                   g[c+6]*d6*inv+b[c+6], g[c+7]*d7*inv+b[c+7]);
}

// ---------------- tf32 MMA GEMM: 32xBN tile, BK=32, 256 threads (8 warps 2x4) -------
// (R13 configuration: single accumulator everywhere; AREG for K=256 paths.)
template<bool RELU, bool RES, bool ROUND, bool LNA, bool AREG, int BN>
__device__ __forceinline__ void gemm_body(
    const float* __restrict__ A, int lda, const float* __restrict__ B, int ldb,
    const float* __restrict__ bias, const float* __restrict__ res,
    float* __restrict__ C, int ldc, int K, int m0, int n0,
    const float* __restrict__ lg, const float* __restrict__ lb)
{
    constexpr int SB = BN + 8;
    constexpr int NS = BN / 32;
    constexpr int BV = BN / 8;
    __shared__ float As[2][32*36];
    __shared__ float Bs[2][32*SB];
    const int tid = threadIdx.x, lane = tid & 31, wid = tid >> 5;
    const int g = lane >> 2, tt = lane & 3;
    const int wm = wid >> 2, wn = wid & 3;
    const int ar = tid >> 3, acol = (tid & 7) * 4;
    const int bkr = tid >> 3;
    const int bnc = (tid & 7) * BV;

    float acc[NS][4];
    #pragma unroll
    for (int j = 0; j < NS; j++)
        #pragma unroll
        for (int q = 0; q < 4; q++) acc[j][q] = 0.f;

    const float* Aptr = A + (size_t)(m0 + ar)*lda + acol;
    const float* Bptr = B + (size_t)bkr*ldb + n0 + bnc;

    float areg[AREG ? 32 : 4];
    if (AREG) {
        #pragma unroll
        for (int c = 0; c < 8; c++)
            *(float4*)&areg[c*4] = *(const float4*)(Aptr + c*32);
        if (LNA) {
            float s = 0.f;
            #pragma unroll
            for (int i = 0; i < 32; i++) s += areg[i];
            #pragma unroll
            for (int o = 1; o < 8; o <<= 1) s += __shfl_xor_sync(0xffffffffu, s, o);
            const float mu = s * (1.f/Dd);
            float q = 0.f;
            #pragma unroll
            for (int i = 0; i < 32; i++) { float d = areg[i]-mu; q += d*d; }
            #pragma unroll
            for (int o = 1; o < 8; o <<= 1) q += __shfl_xor_sync(0xffffffffu, q, o);
            const float inv = 1.f / (sqrtf(q * (1.f/(Dd-1))) + EPSf);
            #pragma unroll
            for (int c = 0; c < 8; c++) {
                float4 g4 = *(const float4*)(lg + c*32 + acol);
                float4 b4 = *(const float4*)(lb + c*32 + acol);
                areg[c*4+0] = tfr(g4.x*(areg[c*4+0]-mu)*inv + b4.x);
                areg[c*4+1] = tfr(g4.y*(areg[c*4+1]-mu)*inv + b4.y);
                areg[c*4+2] = tfr(g4.z*(areg[c*4+2]-mu)*inv + b4.z);
                areg[c*4+3] = tfr(g4.w*(areg[c*4+3]-mu)*inv + b4.w);
            }
        }
    }

    {
        if (AREG) {
            *(float4*)&As[0][ar*36 + acol] = *(float4*)&areg[0];
        } else {
            *(float4*)&As[0][ar*36 + acol] = *(const float4*)Aptr;
        }
        *(float4*)&Bs[0][bkr*SB + bnc] = *(const float4*)Bptr;
        if (BV == 8) *(float4*)&Bs[0][bkr*SB + bnc + 4] = *(const float4*)(Bptr + 4);
    }
    __syncthreads();

    if (AREG) {
        #pragma unroll
        for (int kt = 0; kt < 8; kt++) {
            const int cur = kt & 1;
            const bool nx = kt < 7;
            float4 pb0, pb1;
            if (nx) {
                const float* bp = Bptr + (size_t)(kt+1)*32*ldb;
                pb0 = *(const float4*)bp;
                if (BV == 8) pb1 = *(const float4*)(bp + 4);
            }
            #pragma unroll
            for (int kk = 0; kk < 4; kk++) {
                const int k = kk*8, mb = wm*16;
                uint32_t af[4];
                af[0] = __float_as_uint(As[cur][(mb+g)*36   + k+tt]);
                af[1] = __float_as_uint(As[cur][(mb+g+8)*36 + k+tt]);
                af[2] = __float_as_uint(As[cur][(mb+g)*36   + k+tt+4]);
                af[3] = __float_as_uint(As[cur][(mb+g+8)*36 + k+tt+4]);
                #pragma unroll
                for (int sn = 0; sn < NS; sn++) {
                    const int nb = wn*(BN/4) + sn*8;
                    uint32_t bf[2];
                    bf[0] = __float_as_uint(Bs[cur][(k+tt)*SB + nb+g]);
                    bf[1] = __float_as_uint(Bs[cur][(k+tt+4)*SB + nb+g]);
                    mma_tf32(acc[sn], af, bf);
                }
            }
            if (nx) {
                const int nxt = cur ^ 1;
                *(float4*)&As[nxt][ar*36 + acol] = *(float4*)&areg[(kt+1)*4];
                *(float4*)&Bs[nxt][bkr*SB + bnc] = pb0;
                if (BV == 8) *(float4*)&Bs[nxt][bkr*SB + bnc + 4] = pb1;
            }
            __syncthreads();
        }
    } else {
        const int nkt = K / 32;
        for (int kt = 0; kt < nkt; kt++) {
            const int cur = kt & 1;
            const bool nx = (kt + 1) < nkt;
            float4 pa, pb0, pb1;
            if (nx) {
                pa = *(const float4*)(Aptr + (kt+1)*32);
                const float* bp = Bptr + (size_t)(kt+1)*32*ldb;
                pb0 = *(const float4*)bp;
                if (BV == 8) pb1 = *(const float4*)(bp + 4);
            }
            #pragma unroll
            for (int kk = 0; kk < 4; kk++) {
                const int k = kk*8, mb = wm*16;
                uint32_t af[4];
                af[0] = __float_as_uint(As[cur][(mb+g)*36   + k+tt]);
                af[1] = __float_as_uint(As[cur][(mb+g+8)*36 + k+tt]);
                af[2] = __float_as_uint(As[cur][(mb+g)*36   + k+tt+4]);
                af[3] = __float_as_uint(As[cur][(mb+g+8)*36 + k+tt+4]);
                #pragma unroll
                for (int sn = 0; sn < NS; sn++) {
                    const int nb = wn*(BN/4) + sn*8;
                    uint32_t bf[2];
                    bf[0] = __float_as_uint(Bs[cur][(k+tt)*SB + nb+g]);
                    bf[1] = __float_as_uint(Bs[cur][(k+tt+4)*SB + nb+g]);
                    mma_tf32(acc[sn], af, bf);
                }
            }
            if (nx) {
                const int nxt = cur ^ 1;
                *(float4*)&As[nxt][ar*36 + acol] = pa;
                *(float4*)&Bs[nxt][bkr*SB + bnc] = pb0;
                if (BV == 8) *(float4*)&Bs[nxt][bkr*SB + bnc + 4] = pb1;
            }
            __syncthreads();
        }
    }

    const int r0 = m0 + wm*16 + g;
    #pragma unroll
    for (int sn = 0; sn < NS; sn++) {
        const int cg = n0 + wn*(BN/4) + sn*8 + tt*2;
        float v0 = acc[sn][0] + bias[cg];
        float v1 = acc[sn][1] + bias[cg+1];
        float v2 = acc[sn][2] + bias[cg];
        float v3 = acc[sn][3] + bias[cg+1];
        if (RELU) { v0 = fmaxf(v0,0.f); v1 = fmaxf(v1,0.f); v2 = fmaxf(v2,0.f); v3 = fmaxf(v3,0.f); }
        if (ROUND) { v0 = tfr(v0); v1 = tfr(v1); v2 = tfr(v2); v3 = tfr(v3); }
        if (RES) {
            v0 += res[(size_t)r0*ldc + cg];     v1 += res[(size_t)r0*ldc + cg+1];
            v2 += res[(size_t)(r0+8)*ldc + cg]; v3 += res[(size_t)(r0+8)*ldc + cg+1];
        }
        *(float2*)&C[(size_t)r0*ldc + cg]     = make_float2(v0, v1);
        *(float2*)&C[(size_t)(r0+8)*ldc + cg] = make_float2(v2, v3);
    }
}

template<bool RELU, bool RES, bool ROUND, bool LNA, bool AREG, int BN>
__global__ void __launch_bounds__(256)
gemm_kernel(const float* __restrict__ A, int lda,
            const float* __restrict__ B, int ldb,
            const float* __restrict__ bias,
            const float* __restrict__ res,
            float* __restrict__ C, int ldc, int K,
            const float* __restrict__ lg,
            const float* __restrict__ lb) {
    gemm_body<RELU, RES, ROUND, LNA, AREG, BN>(A, lda, B, ldb, bias, res, C, ldc, K,
                                               blockIdx.y*32, blockIdx.x*BN, lg, lb);
}

__global__ void __launch_bounds__(256)
qkv_kernel(const float* __restrict__ A,
           const float* __restrict__ Wq, const float* __restrict__ Wk,
           const float* __restrict__ Wv,
           const float* __restrict__ bq, const float* __restrict__ bk,
           const float* __restrict__ bv,
           float* __restrict__ Q, float* __restrict__ Km,
           float* __restrict__ V,
           const float* __restrict__ lg,
           const float* __restrict__ lb) {
    const float* B; const float* bias; float* C;
    if (blockIdx.z == 0)      { B = Wq; bias = bq; C = Q;  }
    else if (blockIdx.z == 1) { B = Wk; bias = bk; C = Km; }
    else                      { B = Wv; bias = bv; C = V;  }
    gemm_body<false, false, true, true, true, 64>(A, Dd, B, Dd, bias, nullptr, C, Dd, Dd,
                                                  blockIdx.y*32, blockIdx.x*64, lg, lb);
}

// ---------------- fused relational flash attention: register-P PV (R11 winner) ------
#define BINSTRIDE 1188
__global__ void __launch_bounds__(256, 3)
flash_kernel(const float* __restrict__ Q, const float* __restrict__ Kg,
             const float* __restrict__ Vg,
             const unsigned char* __restrict__ rel8,
             const float* __restrict__ rke, const float* __restrict__ rve,
             float* __restrict__ O)
{
    extern __shared__ float smf[];
    float* Qs    = smf;                 // 32*36
    float* Ks    = Qs    + 32*36;       // 64*36
    float* Vs    = Ks    + 64*36;       // 64*40 (row-permuted)
    float* Ps    = Vs    + 64*40;       // 32*68
    float* qrs   = Ps    + 32*68;       // 32*37 (reused as merged bins)
    float* bins  = qrs   + 32*Rr;       // 4*BINSTRIDE
    float* rks   = bins  + 4*BINSTRIDE; // 37*32
    float* rvs   = rks   + Rr*DKk;      // 37*32
    float* lredS = rvs   + Rr*DKk;      // 128
    float* lrow  = lredS + 128;         // 32
    float* osA   = lrow  + 32;          // 1024
    float* osB   = osA   + 1024;        // 1024

    const int tid  = threadIdx.x;
    const int lane = tid & 31, wid = tid >> 5;
    const int g = lane >> 2, tt = lane & 3;
    const int i0 = blockIdx.x * 32, h = blockIdx.y;
    const int s_wm = wid >> 2, s_wn = wid & 3;

    const int kvr = tid >> 2, kvd = (tid & 3) * 8;
    const int vpr = (kvr & ~7) | ((kvr & 7) >> 1) | ((kvr & 1) << 2);
    const uint32_t ks_a0 = (uint32_t)__cvta_generic_to_shared(&Ks[kvr*36 + kvd]);
    const uint32_t ks_a1 = ks_a0 + 16;
    const uint32_t vs_a0 = (uint32_t)__cvta_generic_to_shared(&Vs[vpr*40 + kvd]);
    const uint32_t vs_a1 = vs_a0 + 16;

    // ---- init ----
    {
        const int r = tid >> 3, dc = (tid & 7) * 4;
        *(float4*)&Qs[r*36 + dc] = *(const float4*)(Q + (size_t)(i0+r)*Dd + h*DKk + dc);
    }
    for (int idx = tid; idx < Rr*DKk; idx += 256) { rks[idx] = rke[idx]; rvs[idx] = rve[idx]; }
    for (int idx = tid; idx < 4*BINSTRIDE; idx += 256) bins[idx] = 0.f;
    __syncthreads();

    for (int p = tid; p < 32*Rr; p += 256) {
        const int row = p / Rr, r = p - row*Rr;
        const float* qrow = Qs + row*36;
        const float* kr   = rks + r*DKk;
        float s = 0.f;
        #pragma unroll
        for (int d = 0; d < DKk; d++) s += qrow[d]*kr[d];
        qrs[row*Rr + r] = s;
    }

    uint32_t af[4][4];
    {
        const int mb = s_wm*16;
        #pragma unroll
        for (int ks = 0; ks < 4; ks++) {
            af[ks][0] = __float_as_uint(Qs[(mb+g)*36   + ks*8+tt]);
            af[ks][1] = __float_as_uint(Qs[(mb+g+8)*36 + ks*8+tt]);
            af[ks][2] = __float_as_uint(Qs[(mb+g)*36   + ks*8+tt+4]);
            af[ks][3] = __float_as_uint(Qs[(mb+g+8)*36 + ks*8+tt+4]);
        }
    }
    float oacc[4][4];
    #pragma unroll
    for (int i = 0; i < 4; i++)
        #pragma unroll
        for (int j = 0; j < 4; j++) oacc[i][j] = 0.f;
    float lp0 = 0.f, lp1 = 0.f;
    const int r0f = s_wm*16 + g, r1f = r0f + 8;

    // prologue: stage K/V tile 0 (V permuted)
    {
        const float* kp = Kg + (size_t)kvr*Dd + h*DKk + kvd;
        const float* vp = Vg + (size_t)kvr*Dd + h*DKk + kvd;
        *(float4*)&Ks[kvr*36 + kvd]     = *(const float4*)kp;
        *(float4*)&Ks[kvr*36 + kvd + 4] = *(const float4*)(kp + 4);
        *(float4*)&Vs[vpr*40 + kvd]     = *(const float4*)vp;
        *(float4*)&Vs[vpr*40 + kvd + 4] = *(const float4*)(vp + 4);
    }
    __syncthreads();

    for (int jt = 0; jt < 16; jt++) {
        const int j0 = jt * 64;

        // S = Q @ K^T  (warp: 16 rows x 16 cols = its k-slice)
        float c[2][4];
        #pragma unroll
        for (int i = 0; i < 2; i++)
            #pragma unroll
            for (int j = 0; j < 4; j++) c[i][j] = 0.f;
        #pragma unroll
        for (int ks = 0; ks < 4; ks++) {
            #pragma unroll
            for (int sn = 0; sn < 2; sn++) {
                const int nb = s_wn*16 + sn*8;
                uint32_t bf[2];
                bf[0] = __float_as_uint(Ks[(nb+g)*36 + ks*8+tt]);
                bf[1] = __float_as_uint(Ks[(nb+g)*36 + ks*8+tt+4]);
                mma_tf32(c[sn], af[ks], bf);
            }
        }

        // exp in fragments; keep tf32 bits for PV A-frags; write Ps for bins pass
        uint32_t pb[2][4];
        {
            const unsigned char* rr0 = rel8 + (size_t)(i0+r0f)*Nn + j0;
            const unsigned char* rr1 = rel8 + (size_t)(i0+r1f)*Nn + j0;
            const float* q0 = qrs + r0f*Rr;
            const float* q1 = qrs + r1f*Rr;
            #pragma unroll
            for (int sn = 0; sn < 2; sn++) {
                const int col = s_wn*16 + sn*8 + tt*2;
                const unsigned int e0 = *(const unsigned short*)(rr0 + col);
                const unsigned int e1 = *(const unsigned short*)(rr1 + col);
                float p00 = __expf(fminf((c[sn][0] + q0[e0 & 0xff])*SCALEf, 80.f));
                float p01 = __expf(fminf((c[sn][1] + q0[e0 >> 8 ])*SCALEf, 80.f));
                float p10 = __expf(fminf((c[sn][2] + q1[e1 & 0xff])*SCALEf, 80.f));
                float p11 = __expf(fminf((c[sn][3] + q1[e1 >> 8 ])*SCALEf, 80.f));
                lp0 += p00 + p01; lp1 += p10 + p11;
                const uint32_t b00 = f2tf(p00), b01 = f2tf(p01);
                const uint32_t b10 = f2tf(p10), b11 = f2tf(p11);
                *(float2*)&Ps[r0f*68 + col] =
                    make_float2(__uint_as_float(b00), __uint_as_float(b01));
                *(float2*)&Ps[r1f*68 + col] =
                    make_float2(__uint_as_float(b10), __uint_as_float(b11));
                pb[sn][0] = b00; pb[sn][1] = b10; pb[sn][2] = b01; pb[sn][3] = b11;
            }
        }

        // O += P @ V' directly from registers: k-slice = own cols
        #pragma unroll
        for (int sn = 0; sn < 2; sn++) {
            const int k = s_wn*16 + sn*8;
            #pragma unroll
            for (int nb = 0; nb < 4; nb++) {
                uint32_t bf[2];
                bf[0] = __float_as_uint(Vs[(k+tt)*40 + nb*8+g]);
                bf[1] = __float_as_uint(Vs[(k+tt+4)*40 + nb*8+g]);
                mma_tf32(oacc[nb], pb[sn], bf);
            }
        }
        __syncthreads();   // sync1: Ps visible; Ks/Vs reads done

        // next K/V via cp.async — overlaps bins pass
        if (jt < 15) {
            const float* kp = Kg + (size_t)(j0+64+kvr)*Dd + h*DKk + kvd;
            const float* vp = Vg + (size_t)(j0+64+kvr)*Dd + h*DKk + kvd;
            asm volatile("cp.async.cg.shared.global [%0], [%1], 16;\n"
                         :: "r"(ks_a0), "l"(kp) : "memory");
            asm volatile("cp.async.cg.shared.global [%0], [%1], 16;\n"
                         :: "r"(ks_a1), "l"(kp + 4) : "memory");
            asm volatile("cp.async.cg.shared.global [%0], [%1], 16;\n"
                         :: "r"(vs_a0), "l"(vp) : "memory");
            asm volatile("cp.async.cg.shared.global [%0], [%1], 16;\n"
                         :: "r"(vs_a1), "l"(vp + 4) : "memory");
            asm volatile("cp.async.commit_group;\n" ::: "memory");
        }

        // bins: 128 threads, 4 replicas, exclusive (row, 16-col segment) — no atomics
        if (tid < 128) {
            const int rp_row = tid >> 2, rp_seg = tid & 3;
            const float* prow = Ps + rp_row*68 + rp_seg*16;
            float* bn = bins + rp_seg*BINSTRIDE + rp_row*Rr;
            uint4 rb = *(const uint4*)(rel8 + (size_t)(i0+rp_row)*Nn + j0 + rp_seg*16);
            const uint32_t rw[4] = {rb.x, rb.y, rb.z, rb.w};
            #pragma unroll
            for (int q4 = 0; q4 < 4; q4++) {
                float4 pv = *(const float4*)(prow + q4*4);
                const uint32_t r4 = rw[q4];
                bn[ r4      & 0xff] += pv.x;
                bn[(r4>> 8) & 0xff] += pv.y;
                bn[(r4>>16) & 0xff] += pv.z;
                bn[(r4>>24)       ] += pv.w;
            }
        }
        if (jt < 15) asm volatile("cp.async.wait_group 0;\n" ::: "memory");
        __syncthreads();   // sync2: bins done; staged K/V visible
    }

    // ---- reductions ----
    lp0 += __shfl_xor_sync(0xffffffffu, lp0, 1);
    lp0 += __shfl_xor_sync(0xffffffffu, lp0, 2);
    lp1 += __shfl_xor_sync(0xffffffffu, lp1, 1);
    lp1 += __shfl_xor_sync(0xffffffffu, lp1, 2);
    if ((lane & 3) == 0) { lredS[s_wn*32 + r0f] = lp0; lredS[s_wn*32 + r1f] = lp1; }
    if (s_wn == 1) {
        float* dst = osA + s_wm*512 + lane*16;
        #pragma unroll
        for (int nb = 0; nb < 4; nb++)
            #pragma unroll
            for (int q = 0; q < 4; q++) dst[nb*4+q] = oacc[nb][q];
    }
    __syncthreads();
    for (int idx = tid; idx < 32*Rr; idx += 256) {
        float s = 0.f;
        #pragma unroll
        for (int q = 0; q < 4; q++) s += bins[q*BINSTRIDE + idx];
        qrs[idx] = s;
    }
    if (tid < 32)
        lrow[tid] = lredS[tid] + lredS[32+tid] + lredS[64+tid] + lredS[96+tid];
    if (s_wn == 0) {
        const float* src = osA + s_wm*512 + lane*16;
        #pragma unroll
        for (int nb = 0; nb < 4; nb++)
            #pragma unroll
            for (int q = 0; q < 4; q++) oacc[nb][q] += src[nb*4+q];
    }
    if (s_wn == 2) {
        float* dst = osB + s_wm*512 + lane*16;
        #pragma unroll
        for (int nb = 0; nb < 4; nb++)
            #pragma unroll
            for (int q = 0; q < 4; q++) dst[nb*4+q] = oacc[nb][q];
    }
    __syncthreads();
    if (s_wn == 0) {
        const float* src = osB + s_wm*512 + lane*16;
        #pragma unroll
        for (int nb = 0; nb < 4; nb++)
            #pragma unroll
            for (int q = 0; q < 4; q++) oacc[nb][q] += src[nb*4+q];
    }
    if (s_wn == 3) {
        float* dst = osA + s_wm*512 + lane*16;
        #pragma unroll
        for (int nb = 0; nb < 4; nb++)
            #pragma unroll
            for (int q = 0; q < 4; q++) dst[nb*4+q] = oacc[nb][q];
    }
    __syncthreads();

    // ---- output: (P@V + bins@rv)/l, tf32-rounded (s_wn==0 warps) ----
    if (s_wn == 0) {
        const float* src = osA + s_wm*512 + lane*16;
        #pragma unroll
        for (int nb = 0; nb < 4; nb++)
            #pragma unroll
            for (int q = 0; q < 4; q++) oacc[nb][q] += src[nb*4+q];
        const float inv0 = 1.f / lrow[r0f];
        const float inv1 = 1.f / lrow[r1f];
        #pragma unroll
        for (int nb = 0; nb < 4; nb++) {
            const int col = nb*8 + tt*2;
            float s00 = 0.f, s01 = 0.f, s10 = 0.f, s11 = 0.f;
            #pragma unroll
            for (int r = 0; r < Rr; r++) {
                const float b0v = qrs[r0f*Rr+r], b1v = qrs[r1f*Rr+r];
                const float rv0 = rvs[r*DKk+col], rv1 = rvs[r*DKk+col+1];
                s00 += b0v*rv0; s01 += b0v*rv1; s10 += b1v*rv0; s11 += b1v*rv1;
            }
            *(float2*)&O[(size_t)(i0+r0f)*Dd + h*DKk + col] =
                make_float2(tfr((oacc[nb][0]+s00)*inv0), tfr((oacc[nb][1]+s01)*inv0));
            *(float2*)&O[(size_t)(i0+r1f)*Dd + h*DKk + col] =
                make_float2(tfr((oacc[nb][2]+s10)*inv1), tfr((oacc[nb][3]+s11)*inv1));
        }
    }
}

// ----------------------------------- host ------------------------------------------
#define FLASH_SMEM ((32*36 + 64*36 + 64*40 + 32*68 + 32*Rr + 4*BINSTRIDE \
                     + Rr*DKk + Rr*DKk + 128 + 32 + 2048) * 4)

extern "C" void kernel_launch(void* const* d_in, const int* in_sizes, int n_in,
                              void* d_out, int out_size) {
    const float* x    = (const float*)d_in[0];
    const int*   rel  = (const int*)  d_in[1];
    const float* Wq   = (const float*)d_in[2],  *bq = (const float*)d_in[3];
    const float* Wk   = (const float*)d_in[4],  *bk = (const float*)d_in[5];
    const float* Wv   = (const float*)d_in[6],  *bv = (const float*)d_in[7];
    const float* Wo   = (const float*)d_in[8],  *bo = (const float*)d_in[9];
    const float* rke  = (const float*)d_in[10], *rve = (const float*)d_in[11];
    const float* W1   = (const float*)d_in[12], *b1 = (const float*)d_in[13];
    const float* W2   = (const float*)d_in[14], *b2 = (const float*)d_in[15];
    const float* ln1g = (const float*)d_in[16], *ln1b = (const float*)d_in[17];
    const float* ln2g = (const float*)d_in[18], *ln2b = (const float*)d_in[19];
    const float* lnfg = (const float*)d_in[20], *lnfb = (const float*)d_in[21];

    float *X, *Q, *Kb, *V, *O, *FFb; unsigned char* R8;
    float *cWq, *cWk, *cWv, *cWo, *cW1, *cW2;
    cudaGetSymbolAddress((void**)&X,   g_X);
    cudaGetSymbolAddress((void**)&Q,   g_Q);
    cudaGetSymbolAddress((void**)&Kb,  g_K);
    cudaGetSymbolAddress((void**)&V,   g_V);
    cudaGetSymbolAddress((void**)&O,   g_O);
    cudaGetSymbolAddress((void**)&FFb, g_FF);
    cudaGetSymbolAddress((void**)&R8,  g_rel8);
    cudaGetSymbolAddress((void**)&cWq, g_Wq);
    cudaGetSymbolAddress((void**)&cWk, g_Wk);
    cudaGetSymbolAddress((void**)&cWv, g_Wv);
    cudaGetSymbolAddress((void**)&cWo, g_Wo);
    cudaGetSymbolAddress((void**)&cW1, g_W1);
    cudaGetSymbolAddress((void**)&cW2, g_W2);

    cudaFuncSetAttribute(flash_kernel, cudaFuncAttributeMaxDynamicSharedMemorySize, FLASH_SMEM);

    prep_kernel<<<2048, 256>>>(rel, R8, Wq, Wk, Wv, Wo, W1, W2,
                               cWq, cWk, cWv, cWo, cW1, cW2);

    for (int l = 0; l < Ll; l++) {
        // layer 0 reads the harness input directly; g_X is first written by Wo's
        // residual epilogue below (X = x + o), so no input memcpy is needed.
        const float* Xin = (l == 0) ? x : X;
        qkv_kernel<<<dim3(Dd/64, Nn/32, 3), 256>>>(Xin,
            cWq + (size_t)l*Dd*Dd, cWk + (size_t)l*Dd*Dd, cWv + (size_t)l*Dd*Dd,
            bq + l*Dd, bk + l*Dd, bv + l*Dd, Q, Kb, V,
            ln1g + l*Dd, ln1b + l*Dd);
        flash_kernel<<<dim3(Nn/32, Hh), 256, FLASH_SMEM>>>(
            Q, Kb, V, R8, rke + (size_t)l*Rr*DKk, rve + (size_t)l*Rr*DKk, O);
        gemm_kernel<false, true, false, false, true, 32><<<dim3(Dd/32, Nn/32), 256>>>(
            O, Dd, cWo + (size_t)l*Dd*Dd, Dd, bo + l*Dd, Xin, X, Dd, Dd,
            nullptr, nullptr);
        gemm_kernel<true, false, true, true, true, 64><<<dim3(FFf/64, Nn/32), 256>>>(
            X, Dd, cW1 + (size_t)l*Dd*FFf, FFf, b1 + l*FFf, nullptr, FFb, FFf, Dd,
            ln2g + l*Dd, ln2b + l*Dd);
        gemm_kernel<false, true, false, false, false, 32><<<dim3(Dd/32, Nn/32), 256>>>(
            FFb, FFf, cW2 + (size_t)l*FFf*Dd, Dd, b2 + l*Dd, X, X, Dd, FFf,
            nullptr, nullptr);
    }
    ln_kernel<<<Nn/8, 256>>>(X, (float*)d_out, lnfg, lnfb);
}

// round 17
// speedup vs baseline: 1.0875x; 1.0079x over previous
#include <cuda_runtime.h>
#include <math.h>
#include <stdint.h>

#define Nn   1024
#define Dd   256
#define Hh   8
#define DKk  32
#define FFf  1024
#define Rr   37
#define Ll   8
#define EPSf 1e-6f
#define SCALEf 0.17677669529663687f  /* 1/sqrt(32) */

// ---------------- scratch (device globals: no allocation allowed) ----------------
__device__ float g_X [Nn*Dd];
__device__ float g_Q [Nn*Dd];
__device__ float g_K [Nn*Dd];
__device__ float g_V [Nn*Dd];
__device__ float g_O [Nn*Dd];
__device__ float g_FF[Nn*FFf];
__device__ unsigned char g_rel8[Nn*Nn];
// tf32-pre-rounded weights
__device__ float g_Wq[Ll*Dd*Dd];
__device__ float g_Wk[Ll*Dd*Dd];
__device__ float g_Wv[Ll*Dd*Dd];
__device__ float g_Wo[Ll*Dd*Dd];
__device__ float g_W1[Ll*Dd*FFf];
__device__ float g_W2[Ll*FFf*Dd];

// ---------------- tf32 helpers -----------------------------------------------------
__device__ __forceinline__ uint32_t f2tf(float f) {
    uint32_t u; asm("cvt.rna.tf32.f32 %0, %1;" : "=r"(u) : "f"(f)); return u;
}
__device__ __forceinline__ float tfr(float f) { return __uint_as_float(f2tf(f)); }
__device__ __forceinline__ void mma_tf32(float* d, const uint32_t* a, const uint32_t* b) {
    asm volatile("mma.sync.aligned.m16n8k8.row.col.f32.tf32.tf32.f32 "
        "{%0,%1,%2,%3}, {%4,%5,%6,%7}, {%8,%9}, {%0,%1,%2,%3};\n"
        : "+f"(d[0]), "+f"(d[1]), "+f"(d[2]), "+f"(d[3])
        : "r"(a[0]), "r"(a[1]), "r"(a[2]), "r"(a[3]), "r"(b[0]), "r"(b[1]));
}

// ---------------- one-time prep (single kernel: rel->u8 + weight rounding) ----------
#define SZ_D (Ll*Dd*Dd/4)
#define SZ_F (Ll*Dd*FFf/4)
#define SZ_R (Nn*Nn/4)
__global__ void prep_kernel(const int* __restrict__ rel, unsigned char* __restrict__ r8,
                            const float* __restrict__ Wq, const float* __restrict__ Wk,
                            const float* __restrict__ Wv, const float* __restrict__ Wo,
                            const float* __restrict__ W1, const float* __restrict__ W2,
                            float* __restrict__ oq, float* __restrict__ ok,
                            float* __restrict__ ov, float* __restrict__ oo,
                            float* __restrict__ o1, float* __restrict__ o2) {
    const int total = 4*SZ_D + 2*SZ_F + SZ_R;
    for (int i = blockIdx.x*256 + threadIdx.x; i < total; i += gridDim.x*256) {
        int j = i;
        if (j < SZ_R) {   // 4 rel ints -> 4 bytes
            int4 v = ((const int4*)rel)[j];
            uchar4 o; o.x=(unsigned char)v.x; o.y=(unsigned char)v.y;
            o.z=(unsigned char)v.z; o.w=(unsigned char)v.w;
            ((uchar4*)r8)[j] = o;
            continue;
        }
        j -= SZ_R;
        const float4* s; float4* d;
        if      (j < SZ_D)            { s = (const float4*)Wq; d = (float4*)oq; }
        else if ((j -= SZ_D) < SZ_D)  { s = (const float4*)Wk; d = (float4*)ok; }
        else if ((j -= SZ_D) < SZ_D)  { s = (const float4*)Wv; d = (float4*)ov; }
        else if ((j -= SZ_D) < SZ_D)  { s = (const float4*)Wo; d = (float4*)oo; }
        else if ((j -= SZ_D) < SZ_F)  { s = (const float4*)W1; d = (float4*)o1; }
        else    { j -= SZ_F;            s = (const float4*)W2; d = (float4*)o2; }
        float4 v = s[j];
        d[j] = make_float4(tfr(v.x), tfr(v.y), tfr(v.z), tfr(v.w));
    }
}

// ---------------- final LayerNorm ---------------------------------------------------
__global__ void ln_kernel(const float* __restrict__ in, float* __restrict__ out,
                          const float* __restrict__ g, const float* __restrict__ b) {
    const int wid = threadIdx.x >> 5, lane = threadIdx.x & 31;
    const int row = blockIdx.x * 8 + wid;
    const float* p = in + (size_t)row * Dd + lane * 8;
    float4 v1 = *(const float4*)p, v2 = *(const float4*)(p + 4);
    float s = v1.x+v1.y+v1.z+v1.w + v2.x+v2.y+v2.z+v2.w;
    #pragma unroll
    for (int o = 16; o > 0; o >>= 1) s += __shfl_xor_sync(0xffffffffu, s, o);
    const float mu = s * (1.f/Dd);
    float d0=v1.x-mu,d1=v1.y-mu,d2=v1.z-mu,d3=v1.w-mu;
    float d4=v2.x-mu,d5=v2.y-mu,d6=v2.z-mu,d7=v2.w-mu;
    float q = d0*d0+d1*d1+d2*d2+d3*d3+d4*d4+d5*d5+d6*d6+d7*d7;
    #pragma unroll
    for (int o = 16; o > 0; o >>= 1) q += __shfl_xor_sync(0xffffffffu, q, o);
    const float inv = 1.f / (sqrtf(q * (1.f/(Dd-1))) + EPSf);
    const int c = lane * 8;
    float* op = out + (size_t)row * Dd + c;
    *(float4*)op = make_float4(g[c+0]*d0*inv+b[c+0], g[c+1]*d1*inv+b[c+1],
                               g[c+2]*d2*inv+b[c+2], g[c+3]*d3*inv+b[c+3]);
    *(float4*)(op+4) = make_float4(g[c+4]*d4*inv+b[c+4], g[c+5]*d5*inv+b[c+5],
                                   g[c+6]*d6*inv+b[c+6], g[c+7]*d7*inv+b[c+7]);
}

// ---------------- tf32 MMA GEMM: 32xBN tile, BK=32, 256 threads (8 warps 2x4) -------
// (R13 configuration — measured local optimum; do not mutate.)
template<bool RELU, bool RES, bool ROUND, bool LNA, bool AREG, int BN>
__device__ __forceinline__ void gemm_body(
    const float* __restrict__ A, int lda, const float* __restrict__ B, int ldb,
    const float* __restrict__ bias, const float* __restrict__ res,
    float* __restrict__ C, int ldc, int K, int m0, int n0,
    const float* __restrict__ lg, const float* __restrict__ lb)
{
    constexpr int SB = BN + 8;
    constexpr int NS = BN / 32;
    constexpr int BV = BN / 8;
    __shared__ float As[2][32*36];
    __shared__ float Bs[2][32*SB];
    const int tid = threadIdx.x, lane = tid & 31, wid = tid >> 5;
    const int g = lane >> 2, tt = lane & 3;
    const int wm = wid >> 2, wn = wid & 3;
    const int ar = tid >> 3, acol = (tid & 7) * 4;
    const int bkr = tid >> 3;
    const int bnc = (tid & 7) * BV;

    float acc[NS][4];
    #pragma unroll
    for (int j = 0; j < NS; j++)
        #pragma unroll
        for (int q = 0; q < 4; q++) acc[j][q] = 0.f;

    const float* Aptr = A + (size_t)(m0 + ar)*lda + acol;
    const float* Bptr = B + (size_t)bkr*ldb + n0 + bnc;

    float areg[AREG ? 32 : 4];
    if (AREG) {
        #pragma unroll
        for (int c = 0; c < 8; c++)
            *(float4*)&areg[c*4] = *(const float4*)(Aptr + c*32);
        if (LNA) {
            float s = 0.f;
            #pragma unroll
            for (int i = 0; i < 32; i++) s += areg[i];
            #pragma unroll
            for (int o = 1; o < 8; o <<= 1) s += __shfl_xor_sync(0xffffffffu, s, o);
            const float mu = s * (1.f/Dd);
            float q = 0.f;
            #pragma unroll
            for (int i = 0; i < 32; i++) { float d = areg[i]-mu; q += d*d; }
            #pragma unroll
            for (int o = 1; o < 8; o <<= 1) q += __shfl_xor_sync(0xffffffffu, q, o);
            const float inv = 1.f / (sqrtf(q * (1.f/(Dd-1))) + EPSf);
            #pragma unroll
            for (int c = 0; c < 8; c++) {
                float4 g4 = *(const float4*)(lg + c*32 + acol);
                float4 b4 = *(const float4*)(lb + c*32 + acol);
                areg[c*4+0] = tfr(g4.x*(areg[c*4+0]-mu)*inv + b4.x);
                areg[c*4+1] = tfr(g4.y*(areg[c*4+1]-mu)*inv + b4.y);
                areg[c*4+2] = tfr(g4.z*(areg[c*4+2]-mu)*inv + b4.z);
                areg[c*4+3] = tfr(g4.w*(areg[c*4+3]-mu)*inv + b4.w);
            }
        }
    }

    {
        if (AREG) {
            *(float4*)&As[0][ar*36 + acol] = *(float4*)&areg[0];
        } else {
            *(float4*)&As[0][ar*36 + acol] = *(const float4*)Aptr;
        }
        *(float4*)&Bs[0][bkr*SB + bnc] = *(const float4*)Bptr;
        if (BV == 8) *(float4*)&Bs[0][bkr*SB + bnc + 4] = *(const float4*)(Bptr + 4);
    }
    __syncthreads();

    if (AREG) {
        #pragma unroll
        for (int kt = 0; kt < 8; kt++) {
            const int cur = kt & 1;
            const bool nx = kt < 7;
            float4 pb0, pb1;
            if (nx) {
                const float* bp = Bptr + (size_t)(kt+1)*32*ldb;
                pb0 = *(const float4*)bp;
                if (BV == 8) pb1 = *(const float4*)(bp + 4);
            }
            #pragma unroll
            for (int kk = 0; kk < 4; kk++) {
                const int k = kk*8, mb = wm*16;
                uint32_t af[4];
                af[0] = __float_as_uint(As[cur][(mb+g)*36   + k+tt]);
                af[1] = __float_as_uint(As[cur][(mb+g+8)*36 + k+tt]);
                af[2] = __float_as_uint(As[cur][(mb+g)*36   + k+tt+4]);
                af[3] = __float_as_uint(As[cur][(mb+g+8)*36 + k+tt+4]);
                #pragma unroll
                for (int sn = 0; sn < NS; sn++) {
                    const int nb = wn*(BN/4) + sn*8;
                    uint32_t bf[2];
                    bf[0] = __float_as_uint(Bs[cur][(k+tt)*SB + nb+g]);
                    bf[1] = __float_as_uint(Bs[cur][(k+tt+4)*SB + nb+g]);
                    mma_tf32(acc[sn], af, bf);
                }
            }
            if (nx) {
                const int nxt = cur ^ 1;
                *(float4*)&As[nxt][ar*36 + acol] = *(float4*)&areg[(kt+1)*4];
                *(float4*)&Bs[nxt][bkr*SB + bnc] = pb0;
                if (BV == 8) *(float4*)&Bs[nxt][bkr*SB + bnc + 4] = pb1;
            }
            __syncthreads();
        }
    } else {
        const int nkt = K / 32;
        for (int kt = 0; kt < nkt; kt++) {
            const int cur = kt & 1;
            const bool nx = (kt + 1) < nkt;
            float4 pa, pb0, pb1;
            if (nx) {
                pa = *(const float4*)(Aptr + (kt+1)*32);
                const float* bp = Bptr + (size_t)(kt+1)*32*ldb;
                pb0 = *(const float4*)bp;
                if (BV == 8) pb1 = *(const float4*)(bp + 4);
            }
            #pragma unroll
            for (int kk = 0; kk < 4; kk++) {
                const int k = kk*8, mb = wm*16;
                uint32_t af[4];
                af[0] = __float_as_uint(As[cur][(mb+g)*36   + k+tt]);
                af[1] = __float_as_uint(As[cur][(mb+g+8)*36 + k+tt]);
                af[2] = __float_as_uint(As[cur][(mb+g)*36   + k+tt+4]);
                af[3] = __float_as_uint(As[cur][(mb+g+8)*36 + k+tt+4]);
                #pragma unroll
                for (int sn = 0; sn < NS; sn++) {
                    const int nb = wn*(BN/4) + sn*8;
                    uint32_t bf[2];
                    bf[0] = __float_as_uint(Bs[cur][(k+tt)*SB + nb+g]);
                    bf[1] = __float_as_uint(Bs[cur][(k+tt+4)*SB + nb+g]);
                    mma_tf32(acc[sn], af, bf);
                }
            }
            if (nx) {
                const int nxt = cur ^ 1;
                *(float4*)&As[nxt][ar*36 + acol] = pa;
                *(float4*)&Bs[nxt][bkr*SB + bnc] = pb0;
                if (BV == 8) *(float4*)&Bs[nxt][bkr*SB + bnc + 4] = pb1;
            }
            __syncthreads();
        }
    }

    const int r0 = m0 + wm*16 + g;
    #pragma unroll
    for (int sn = 0; sn < NS; sn++) {
        const int cg = n0 + wn*(BN/4) + sn*8 + tt*2;
        float v0 = acc[sn][0] + bias[cg];
        float v1 = acc[sn][1] + bias[cg+1];
        float v2 = acc[sn][2] + bias[cg];
        float v3 = acc[sn][3] + bias[cg+1];
        if (RELU) { v0 = fmaxf(v0,0.f); v1 = fmaxf(v1,0.f); v2 = fmaxf(v2,0.f); v3 = fmaxf(v3,0.f); }
        if (ROUND) { v0 = tfr(v0); v1 = tfr(v1); v2 = tfr(v2); v3 = tfr(v3); }
        if (RES) {
            v0 += res[(size_t)r0*ldc + cg];     v1 += res[(size_t)r0*ldc + cg+1];
            v2 += res[(size_t)(r0+8)*ldc + cg]; v3 += res[(size_t)(r0+8)*ldc + cg+1];
        }
        *(float2*)&C[(size_t)r0*ldc + cg]     = make_float2(v0, v1);
        *(float2*)&C[(size_t)(r0+8)*ldc + cg] = make_float2(v2, v3);
    }
}

template<bool RELU, bool RES, bool ROUND, bool LNA, bool AREG, int BN>
__global__ void __launch_bounds__(256)
gemm_kernel(const float* __restrict__ A, int lda,
            const float* __restrict__ B, int ldb,
            const float* __restrict__ bias,
            const float* __restrict__ res,
            float* __restrict__ C, int ldc, int K,
            const float* __restrict__ lg,
            const float* __restrict__ lb) {
    gemm_body<RELU, RES, ROUND, LNA, AREG, BN>(A, lda, B, ldb, bias, res, C, ldc, K,
                                               blockIdx.y*32, blockIdx.x*BN, lg, lb);
}

__global__ void __launch_bounds__(256)
qkv_kernel(const float* __restrict__ A,
           const float* __restrict__ Wq, const float* __restrict__ Wk,
           const float* __restrict__ Wv,
           const float* __restrict__ bq, const float* __restrict__ bk,
           const float* __restrict__ bv,
           float* __restrict__ Q, float* __restrict__ Km,
           float* __restrict__ V,
           const float* __restrict__ lg,
           const float* __restrict__ lb) {
    const float* B; const float* bias; float* C;
    if (blockIdx.z == 0)      { B = Wq; bias = bq; C = Q;  }
    else if (blockIdx.z == 1) { B = Wk; bias = bk; C = Km; }
    else                      { B = Wv; bias = bv; C = V;  }
    gemm_body<false, false, true, true, true, 64>(A, Dd, B, Dd, bias, nullptr, C, Dd, Dd,
                                                  blockIdx.y*32, blockIdx.x*64, lg, lb);
}

// ---------------- fused relational flash attention: register-P PV -------------------
// Changes vs 825.7 build: launch bounds (256,2) (grid-limited to <2 blocks/SM anyway;
// frees the register cap) and rel8 loads prefetched one j-tile ahead (they depend only
// on jt, so the ~234-cyc L2 latency hides under the previous tile's mma/exp work).
#define BINSTRIDE 1188
__global__ void __launch_bounds__(256, 2)
flash_kernel(const float* __restrict__ Q, const float* __restrict__ Kg,
             const float* __restrict__ Vg,
             const unsigned char* __restrict__ rel8,
             const float* __restrict__ rke, const float* __restrict__ rve,
             float* __restrict__ O)
{
    extern __shared__ float smf[];
    float* Qs    = smf;                 // 32*36
    float* Ks    = Qs    + 32*36;       // 64*36
    float* Vs    = Ks    + 64*36;       // 64*40 (row-permuted)
    float* Ps    = Vs    + 64*40;       // 32*68
    float* qrs   = Ps    + 32*68;       // 32*37 (reused as merged bins)
    float* bins  = qrs   + 32*Rr;       // 4*BINSTRIDE
    float* rks   = bins  + 4*BINSTRIDE; // 37*32
    float* rvs   = rks   + Rr*DKk;      // 37*32
    float* lredS = rvs   + Rr*DKk;      // 128
    float* lrow  = lredS + 128;         // 32
    float* osA   = lrow  + 32;          // 1024
    float* osB   = osA   + 1024;        // 1024

    const int tid  = threadIdx.x;
    const int lane = tid & 31, wid = tid >> 5;
    const int g = lane >> 2, tt = lane & 3;
    const int i0 = blockIdx.x * 32, h = blockIdx.y;
    const int s_wm = wid >> 2, s_wn = wid & 3;

    const int kvr = tid >> 2, kvd = (tid & 3) * 8;
    const int vpr = (kvr & ~7) | ((kvr & 7) >> 1) | ((kvr & 1) << 2);
    const uint32_t ks_a0 = (uint32_t)__cvta_generic_to_shared(&Ks[kvr*36 + kvd]);
    const uint32_t ks_a1 = ks_a0 + 16;
    const uint32_t vs_a0 = (uint32_t)__cvta_generic_to_shared(&Vs[vpr*40 + kvd]);
    const uint32_t vs_a1 = vs_a0 + 16;

    // ---- init ----
    {
        const int r = tid >> 3, dc = (tid & 7) * 4;
        *(float4*)&Qs[r*36 + dc] = *(const float4*)(Q + (size_t)(i0+r)*Dd + h*DKk + dc);
    }
    for (int idx = tid; idx < Rr*DKk; idx += 256) { rks[idx] = rke[idx]; rvs[idx] = rve[idx]; }
    for (int idx = tid; idx < 4*BINSTRIDE; idx += 256) bins[idx] = 0.f;
    __syncthreads();

    for (int p = tid; p < 32*Rr; p += 256) {
        const int row = p / Rr, r = p - row*Rr;
        const float* qrow = Qs + row*36;
        const float* kr   = rks + r*DKk;
        float s = 0.f;
        #pragma unroll
        for (int d = 0; d < DKk; d++) s += qrow[d]*kr[d];
        qrs[row*Rr + r] = s;
    }

    uint32_t af[4][4];
    {
        const int mb = s_wm*16;
        #pragma unroll
        for (int ks = 0; ks < 4; ks++) {
            af[ks][0] = __float_as_uint(Qs[(mb+g)*36   + ks*8+tt]);
            af[ks][1] = __float_as_uint(Qs[(mb+g+8)*36 + ks*8+tt]);
            af[ks][2] = __float_as_uint(Qs[(mb+g)*36   + ks*8+tt+4]);
            af[ks][3] = __float_as_uint(Qs[(mb+g+8)*36 + ks*8+tt+4]);
        }
    }
    float oacc[4][4];
    #pragma unroll
    for (int i = 0; i < 4; i++)
        #pragma unroll
        for (int j = 0; j < 4; j++) oacc[i][j] = 0.f;
    float lp0 = 0.f, lp1 = 0.f;
    const int r0f = s_wm*16 + g, r1f = r0f + 8;

    // rel8 base pointers + prefetch state (addresses depend only on jt)
    const unsigned char* relr0 = rel8 + (size_t)(i0+r0f)*Nn;
    const unsigned char* relr1 = rel8 + (size_t)(i0+r1f)*Nn;
    const unsigned char* relrb = rel8 + (size_t)(i0+(tid>>2))*Nn + (tid&3)*16;
    uint32_t ce0[2], ce1[2]; uint4 crb;
    {
        #pragma unroll
        for (int sn = 0; sn < 2; sn++) {
            const int col = s_wn*16 + sn*8 + tt*2;
            ce0[sn] = *(const unsigned short*)(relr0 + col);
            ce1[sn] = *(const unsigned short*)(relr1 + col);
        }
        if (tid < 128) crb = *(const uint4*)relrb;
    }

    // prologue: stage K/V tile 0 (V permuted)
    {
        const float* kp = Kg + (size_t)kvr*Dd + h*DKk + kvd;
        const float* vp = Vg + (size_t)kvr*Dd + h*DKk + kvd;
        *(float4*)&Ks[kvr*36 + kvd]     = *(const float4*)kp;
        *(float4*)&Ks[kvr*36 + kvd + 4] = *(const float4*)(kp + 4);
        *(float4*)&Vs[vpr*40 + kvd]     = *(const float4*)vp;
        *(float4*)&Vs[vpr*40 + kvd + 4] = *(const float4*)(vp + 4);
    }
    __syncthreads();

    for (int jt = 0; jt < 16; jt++) {
        const int j0 = jt * 64;

        // issue rel prefetch for jt+1 (independent of all current-jt work)
        uint32_t ne0[2], ne1[2]; uint4 nrb;
        if (jt < 15) {
            const int j1 = j0 + 64;
            #pragma unroll
            for (int sn = 0; sn < 2; sn++) {
                const int col = s_wn*16 + sn*8 + tt*2;
                ne0[sn] = *(const unsigned short*)(relr0 + j1 + col);
                ne1[sn] = *(const unsigned short*)(relr1 + j1 + col);
            }
            if (tid < 128) nrb = *(const uint4*)(relrb + j1);
        }

        // S = Q @ K^T  (warp: 16 rows x 16 cols = its k-slice)
        float c[2][4];
        #pragma unroll
        for (int i = 0; i < 2; i++)
            #pragma unroll
            for (int j = 0; j < 4; j++) c[i][j] = 0.f;
        #pragma unroll
        for (int ks = 0; ks < 4; ks++) {
            #pragma unroll
            for (int sn = 0; sn < 2; sn++) {
                const int nb = s_wn*16 + sn*8;
                uint32_t bf[2];
                bf[0] = __float_as_uint(Ks[(nb+g)*36 + ks*8+tt]);
                bf[1] = __float_as_uint(Ks[(nb+g)*36 + ks*8+tt+4]);
                mma_tf32(c[sn], af[ks], bf);
            }
        }

        // exp in fragments (rel indices already in registers); P(tf32)->Ps + PV frags
        uint32_t pb[2][4];
        {
            const float* q0 = qrs + r0f*Rr;
            const float* q1 = qrs + r1f*Rr;
            #pragma unroll
            for (int sn = 0; sn < 2; sn++) {
                const int col = s_wn*16 + sn*8 + tt*2;
                const unsigned int e0 = ce0[sn];
                const unsigned int e1 = ce1[sn];
                float p00 = __expf(fminf((c[sn][0] + q0[e0 & 0xff])*SCALEf, 80.f));
                float p01 = __expf(fminf((c[sn][1] + q0[e0 >> 8 ])*SCALEf, 80.f));
                float p10 = __expf(fminf((c[sn][2] + q1[e1 & 0xff])*SCALEf, 80.f));
                float p11 = __expf(fminf((c[sn][3] + q1[e1 >> 8 ])*SCALEf, 80.f));
                lp0 += p00 + p01; lp1 += p10 + p11;
                const uint32_t b00 = f2tf(p00), b01 = f2tf(p01);
                const uint32_t b10 = f2tf(p10), b11 = f2tf(p11);
                *(float2*)&Ps[r0f*68 + col] =
                    make_float2(__uint_as_float(b00), __uint_as_float(b01));
                *(float2*)&Ps[r1f*68 + col] =
                    make_float2(__uint_as_float(b10), __uint_as_float(b11));
                pb[sn][0] = b00; pb[sn][1] = b10; pb[sn][2] = b01; pb[sn][3] = b11;
            }
        }

        // O += P @ V' directly from registers: k-slice = own cols
        #pragma unroll
        for (int sn = 0; sn < 2; sn++) {
            const int k = s_wn*16 + sn*8;
            #pragma unroll
            for (int nb = 0; nb < 4; nb++) {
                uint32_t bf[2];
                bf[0] = __float_as_uint(Vs[(k+tt)*40 + nb*8+g]);
                bf[1] = __float_as_uint(Vs[(k+tt+4)*40 + nb*8+g]);
                mma_tf32(oacc[nb], pb[sn], bf);
            }
        }
        __syncthreads();   // sync1: Ps visible; Ks/Vs reads done

        // next K/V via cp.async — overlaps bins pass
        if (jt < 15) {
            const float* kp = Kg + (size_t)(j0+64+kvr)*Dd + h*DKk + kvd;
            const float* vp = Vg + (size_t)(j0+64+kvr)*Dd + h*DKk + kvd;
            asm volatile("cp.async.cg.shared.global [%0], [%1], 16;\n"
                         :: "r"(ks_a0), "l"(kp) : "memory");
            asm volatile("cp.async.cg.shared.global [%0], [%1], 16;\n"
                         :: "r"(ks_a1), "l"(kp + 4) : "memory");
            asm volatile("cp.async.cg.shared.global [%0], [%1], 16;\n"
                         :: "r"(vs_a0), "l"(vp) : "memory");
            asm volatile("cp.async.cg.shared.global [%0], [%1], 16;\n"
                         :: "r"(vs_a1), "l"(vp + 4) : "memory");
            asm volatile("cp.async.commit_group;\n" ::: "memory");
        }

        // bins: 128 threads, 4 replicas, exclusive (row, 16-col segment) — no atomics
        if (tid < 128) {
            const int rp_row = tid >> 2, rp_seg = tid & 3;
            const float* prow = Ps + rp_row*68 + rp_seg*16;
            float* bn = bins + rp_seg*BINSTRIDE + rp_row*Rr;
            const uint32_t rw[4] = {crb.x, crb.y, crb.z, crb.w};
            #pragma unroll
            for (int q4 = 0; q4 < 4; q4++) {
                float4 pv = *(const float4*)(prow + q4*4);
                const uint32_t r4 = rw[q4];
                bn[ r4      & 0xff] += pv.x;
                bn[(r4>> 8) & 0xff] += pv.y;
                bn[(r4>>16) & 0xff] += pv.z;
                bn[(r4>>24)       ] += pv.w;
            }
        }
        if (jt < 15) asm volatile("cp.async.wait_group 0;\n" ::: "memory");
        __syncthreads();   // sync2: bins done; staged K/V visible

        if (jt < 15) {
            ce0[0] = ne0[0]; ce0[1] = ne0[1];
            ce1[0] = ne1[0]; ce1[1] = ne1[1];
            crb = nrb;
        }
    }

    // ---- reductions ----
    lp0 += __shfl_xor_sync(0xffffffffu, lp0, 1);
    lp0 += __shfl_xor_sync(0xffffffffu, lp0, 2);
    lp1 += __shfl_xor_sync(0xffffffffu, lp1, 1);
    lp1 += __shfl_xor_sync(0xffffffffu, lp1, 2);
    if ((lane & 3) == 0) { lredS[s_wn*32 + r0f] = lp0; lredS[s_wn*32 + r1f] = lp1; }
    if (s_wn == 1) {
        float* dst = osA + s_wm*512 + lane*16;
        #pragma unroll
        for (int nb = 0; nb < 4; nb++)
            #pragma unroll
            for (int q = 0; q < 4; q++) dst[nb*4+q] = oacc[nb][q];
    }
    __syncthreads();
    for (int idx = tid; idx < 32*Rr; idx += 256) {
        float s = 0.f;
        #pragma unroll
        for (int q = 0; q < 4; q++) s += bins[q*BINSTRIDE + idx];
        qrs[idx] = s;
    }
    if (tid < 32)
        lrow[tid] = lredS[tid] + lredS[32+tid] + lredS[64+tid] + lredS[96+tid];
    if (s_wn == 0) {
        const float* src = osA + s_wm*512 + lane*16;
        #pragma unroll
        for (int nb = 0; nb < 4; nb++)
            #pragma unroll
            for (int q = 0; q < 4; q++) oacc[nb][q] += src[nb*4+q];
    }
    if (s_wn == 2) {
        float* dst = osB + s_wm*512 + lane*16;
        #pragma unroll
        for (int nb = 0; nb < 4; nb++)
            #pragma unroll
            for (int q = 0; q < 4; q++) dst[nb*4+q] = oacc[nb][q];
    }
    __syncthreads();
    if (s_wn == 0) {
        const float* src = osB + s_wm*512 + lane*16;
        #pragma unroll
        for (int nb = 0; nb < 4; nb++)
            #pragma unroll
            for (int q = 0; q < 4; q++) oacc[nb][q] += src[nb*4+q];
    }
    if (s_wn == 3) {
        float* dst = osA + s_wm*512 + lane*16;
        #pragma unroll
        for (int nb = 0; nb < 4; nb++)
            #pragma unroll
            for (int q = 0; q < 4; q++) dst[nb*4+q] = oacc[nb][q];
    }
    __syncthreads();

    // ---- output: (P@V + bins@rv)/l, tf32-rounded (s_wn==0 warps) ----
    if (s_wn == 0) {
        const float* src = osA + s_wm*512 + lane*16;
        #pragma unroll
        for (int nb = 0; nb < 4; nb++)
            #pragma unroll
            for (int q = 0; q < 4; q++) oacc[nb][q] += src[nb*4+q];
        const float inv0 = 1.f / lrow[r0f];
        const float inv1 = 1.f / lrow[r1f];
        #pragma unroll
        for (int nb = 0; nb < 4; nb++) {
            const int col = nb*8 + tt*2;
            float s00 = 0.f, s01 = 0.f, s10 = 0.f, s11 = 0.f;
            #pragma unroll
            for (int r = 0; r < Rr; r++) {
                const float b0v = qrs[r0f*Rr+r], b1v = qrs[r1f*Rr+r];
                const float rv0 = rvs[r*DKk+col], rv1 = rvs[r*DKk+col+1];
                s00 += b0v*rv0; s01 += b0v*rv1; s10 += b1v*rv0; s11 += b1v*rv1;
            }
            *(float2*)&O[(size_t)(i0+r0f)*Dd + h*DKk + col] =
                make_float2(tfr((oacc[nb][0]+s00)*inv0), tfr((oacc[nb][1]+s01)*inv0));
            *(float2*)&O[(size_t)(i0+r1f)*Dd + h*DKk + col] =
                make_float2(tfr((oacc[nb][2]+s10)*inv1), tfr((oacc[nb][3]+s11)*inv1));
        }
    }
}

// ----------------------------------- host ------------------------------------------
#define FLASH_SMEM ((32*36 + 64*36 + 64*40 + 32*68 + 32*Rr + 4*BINSTRIDE \
                     + Rr*DKk + Rr*DKk + 128 + 32 + 2048) * 4)

extern "C" void kernel_launch(void* const* d_in, const int* in_sizes, int n_in,
                              void* d_out, int out_size) {
    const float* x    = (const float*)d_in[0];
    const int*   rel  = (const int*)  d_in[1];
    const float* Wq   = (const float*)d_in[2],  *bq = (const float*)d_in[3];
    const float* Wk   = (const float*)d_in[4],  *bk = (const float*)d_in[5];
    const float* Wv   = (const float*)d_in[6],  *bv = (const float*)d_in[7];
    const float* Wo   = (const float*)d_in[8],  *bo = (const float*)d_in[9];
    const float* rke  = (const float*)d_in[10], *rve = (const float*)d_in[11];
    const float* W1   = (const float*)d_in[12], *b1 = (const float*)d_in[13];
    const float* W2   = (const float*)d_in[14], *b2 = (const float*)d_in[15];
    const float* ln1g = (const float*)d_in[16], *ln1b = (const float*)d_in[17];
    const float* ln2g = (const float*)d_in[18], *ln2b = (const float*)d_in[19];
    const float* lnfg = (const float*)d_in[20], *lnfb = (const float*)d_in[21];

    float *X, *Q, *Kb, *V, *O, *FFb; unsigned char* R8;
    float *cWq, *cWk, *cWv, *cWo, *cW1, *cW2;
    cudaGetSymbolAddress((void**)&X,   g_X);
    cudaGetSymbolAddress((void**)&Q,   g_Q);
    cudaGetSymbolAddress((void**)&Kb,  g_K);
    cudaGetSymbolAddress((void**)&V,   g_V);
    cudaGetSymbolAddress((void**)&O,   g_O);
    cudaGetSymbolAddress((void**)&FFb, g_FF);
    cudaGetSymbolAddress((void**)&R8,  g_rel8);
    cudaGetSymbolAddress((void**)&cWq, g_Wq);
    cudaGetSymbolAddress((void**)&cWk, g_Wk);
    cudaGetSymbolAddress((void**)&cWv, g_Wv);
    cudaGetSymbolAddress((void**)&cWo, g_Wo);
    cudaGetSymbolAddress((void**)&cW1, g_W1);
    cudaGetSymbolAddress((void**)&cW2, g_W2);

    cudaFuncSetAttribute(flash_kernel, cudaFuncAttributeMaxDynamicSharedMemorySize, FLASH_SMEM);

    prep_kernel<<<2048, 256>>>(rel, R8, Wq, Wk, Wv, Wo, W1, W2,
                               cWq, cWk, cWv, cWo, cW1, cW2);

    for (int l = 0; l < Ll; l++) {
        const float* Xin = (l == 0) ? x : X;
        qkv_kernel<<<dim3(Dd/64, Nn/32, 3), 256>>>(Xin,
            cWq + (size_t)l*Dd*Dd, cWk + (size_t)l*Dd*Dd, cWv + (size_t)l*Dd*Dd,
            bq + l*Dd, bk + l*Dd, bv + l*Dd, Q, Kb, V,
            ln1g + l*Dd, ln1b + l*Dd);
        flash_kernel<<<dim3(Nn/32, Hh), 256, FLASH_SMEM>>>(
            Q, Kb, V, R8, rke + (size_t)l*Rr*DKk, rve + (size_t)l*Rr*DKk, O);
        gemm_kernel<false, true, false, false, true, 32><<<dim3(Dd/32, Nn/32), 256>>>(
            O, Dd, cWo + (size_t)l*Dd*Dd, Dd, bo + l*Dd, Xin, X, Dd, Dd,
            nullptr, nullptr);
        gemm_kernel<true, false, true, true, true, 64><<<dim3(FFf/64, Nn/32), 256>>>(
            X, Dd, cW1 + (size_t)l*Dd*FFf, FFf, b1 + l*FFf, nullptr, FFb, FFf, Dd,
            ln2g + l*Dd, ln2b + l*Dd);
        gemm_kernel<false, true, false, false, false, 32><<<dim3(Dd/32, Nn/32), 256>>>(
            FFb, FFf, cW2 + (size_t)l*FFf*Dd, Dd, b2 + l*Dd, X, X, Dd, FFf,
            nullptr, nullptr);
    }
    ln_kernel<<<Nn/8, 256>>>(X, (float*)d_out, lnfg, lnfb);
}